// round 15
// baseline (speedup 1.0000x reference)
#include <cuda_runtime.h>
#include <cuda_bf16.h>
#include <math.h>
#include <stdint.h>

#define Bq    1024
#define NF    128
#define D     256
#define DI    512
#define NC    100000
#define CTX   96
#define KSEL  128
#define NCLS  10
#define CAPK  3584
#define BCTX  (Bq * CTX)

// ---------------------------------------------------------------------------
// Device scratch
// ---------------------------------------------------------------------------
__device__ float g_Wc [NF * D];          // composed W_lin @ W_K
__device__ float g_bc [D];               // composed bias
__device__ float g_ki [(size_t)NC * D];
__device__ float g_nn [NC];
__device__ float g_x  [Bq * D];
__device__ float g_k  [Bq * D];
__device__ float g_kk [Bq];
__device__ float g_d2 [(size_t)Bq * NC];
__device__ float g_V  [(size_t)BCTX * D];
__device__ float g_xr [Bq * D];
__device__ float g_ln [Bq * D];
__device__ float g_p1 [Bq * DI];
__device__ float g_x2 [Bq * D];
__device__ float g_S  [Bq * CTX];
__device__ float g_w  [Bq * CTX];
__device__ int   g_I2 [Bq * KSEL];
__device__ int   g_I  [Bq * CTX];
__device__ int   g_cls[Bq * CTX];
// bf16 split planes (h = bf16(x), l = bf16(x - h))
__device__ __nv_bfloat16 g_kbh[Bq * D],            g_kbl[Bq * D];
__device__ __nv_bfloat16 g_kih[(size_t)NC * D],    g_kil[(size_t)NC * D];
__device__ __nv_bfloat16 g_T1h[(size_t)DI * D],    g_T1l[(size_t)DI * D];
__device__ __nv_bfloat16 g_T2h[(size_t)D * DI],    g_T2l[(size_t)D * DI];
__device__ __nv_bfloat16 g_dfh[(size_t)BCTX * D],  g_dfl[(size_t)BCTX * D];
__device__ __nv_bfloat16 g_mhh[(size_t)BCTX * DI], g_mhl[(size_t)BCTX * DI];

// ---------------------------------------------------------------------------
// Warp MMA / cp.async helpers (baseline PTX, sm_80+)
// ---------------------------------------------------------------------------
__device__ __forceinline__ uint32_t smem_u32(const void* p) {
    uint32_t a;
    asm("{ .reg .u64 t; cvta.to.shared.u64 t, %1; cvt.u32.u64 %0, t; }" : "=r"(a) : "l"(p));
    return a;
}
__device__ __forceinline__ void ldm_x4(uint32_t* r, uint32_t addr) {
    asm volatile("ldmatrix.sync.aligned.m8n8.x4.shared.b16 {%0,%1,%2,%3}, [%4];"
                 : "=r"(r[0]), "=r"(r[1]), "=r"(r[2]), "=r"(r[3]) : "r"(addr));
}
__device__ __forceinline__ void mma16816(float* c, const uint32_t* a, uint32_t b0, uint32_t b1) {
    asm volatile(
        "mma.sync.aligned.m16n8k16.row.col.f32.bf16.bf16.f32 "
        "{%0,%1,%2,%3}, {%4,%5,%6,%7}, {%8,%9}, {%0,%1,%2,%3};"
        : "+f"(c[0]), "+f"(c[1]), "+f"(c[2]), "+f"(c[3])
        : "r"(a[0]), "r"(a[1]), "r"(a[2]), "r"(a[3]), "r"(b0), "r"(b1));
}
__device__ __forceinline__ void cp16(uint32_t saddr, const void* g, bool pred) {
    int sz = pred ? 16 : 0;
    asm volatile("cp.async.cg.shared.global [%0], [%1], 16, %2;"
                 :: "r"(saddr), "l"(g), "r"(sz));
}
#define CP_COMMIT() asm volatile("cp.async.commit_group;" ::: "memory")

// mode flags
#define F_CF   1
#define F_SP2  2
#define F_RELU 8
#define F_BIAS 16
#define F_DIST 32

#define SROW 40     // smem row stride in halves (80B, 16B-aligned)
#define PSZ  (128 * SROW)       // one plane tile in halves
#define SMH  (2 * 4 * PSZ * 2)  // bytes: 2 bufs x 4 planes = 81920

// ---------------------------------------------------------------------------
// Split-bf16 NT GEMM, cp.async double-buffered, fragment-cached.
// C[m,n] ~= A0*B0 + A0*B1 + A1*B0 (2-plane, 3-product; rel err ~1.5e-5).
// Tile 128x128, BK=32, 256 threads (8 warps: 4M x 2N of 32x64).
// swapxy: m-tile from blockIdx.x, n-tile from blockIdx.y (L2 reuse for dist).
// ---------------------------------------------------------------------------
__global__ void __launch_bounds__(256) hmma_nt(
    int M, int N, int K,
    const __nv_bfloat16* __restrict__ A0, const __nv_bfloat16* __restrict__ A1,
    const __nv_bfloat16* __restrict__ B0, const __nv_bfloat16* __restrict__ B1,
    const float* __restrict__ bias, const float* __restrict__ an2,
    const float* __restrict__ bn2,
    float* __restrict__ Cf, __nv_bfloat16* __restrict__ C0,
    __nv_bfloat16* __restrict__ C1, int mode, int swapxy)
{
    extern __shared__ __align__(16) __nv_bfloat16 sm[];

    const int t    = threadIdx.x;
    const int lane = t & 31;
    const int wid  = t >> 5;
    const int wm   = wid & 3;
    const int wn   = wid >> 2;
    const int m0   = (swapxy ? blockIdx.x : blockIdx.y) * 128;
    const int n0   = (swapxy ? blockIdx.y : blockIdx.x) * 128;

    float acc[2][8][4];
#pragma unroll
    for (int i = 0; i < 2; i++)
#pragma unroll
        for (int j = 0; j < 8; j++)
#pragma unroll
            for (int r = 0; r < 4; r++) acc[i][j][r] = 0.f;

    const __nv_bfloat16* G[4] = {A0, A1, B0, B1};
    const uint32_t sbase = smem_u32(sm);

    const int l_row = t >> 1;
    const int l_q0  = (t & 1) * 2;
    auto issue = [&](int ch, int buf) {
        const int k0 = ch << 5;
        const uint32_t bofs = (uint32_t)buf * 4 * PSZ * 2;
#pragma unroll
        for (int pl = 0; pl < 4; pl++) {
            const bool isA = (pl < 2);
            const int  grow = (isA ? m0 : n0) + l_row;
            const bool ok   = isA ? (grow < M) : (grow < N);
            const __nv_bfloat16* src = G[pl] + (size_t)grow * K + k0 + l_q0 * 8;
            const uint32_t dst = sbase + bofs +
                ((uint32_t)pl * PSZ + (uint32_t)l_row * SROW + l_q0 * 8) * 2;
            cp16(dst,     src,     ok);
            cp16(dst + 16, src + 8, ok);
        }
        CP_COMMIT();
    };

    const int nchunk = K >> 5;
    issue(0, 0);

    for (int ch = 0; ch < nchunk; ch++) {
        const int buf  = ch & 1;
        const bool more = (ch + 1 < nchunk);
        if (more) issue(ch + 1, buf ^ 1);
        if (more) asm volatile("cp.async.wait_group 1;" ::: "memory");
        else      asm volatile("cp.async.wait_group 0;" ::: "memory");
        __syncthreads();

        const uint32_t bb = sbase + (uint32_t)buf * 4 * PSZ * 2;
#pragma unroll
        for (int ks = 0; ks < 2; ks++) {
            uint32_t af[2][2][4];
#pragma unroll
            for (int pl = 0; pl < 2; pl++)
#pragma unroll
                for (int i = 0; i < 2; i++) {
                    const int arow = wm * 32 + i * 16 + (lane & 15);
                    const int acol = ks * 16 + (lane >> 4) * 8;
                    ldm_x4(af[pl][i],
                           bb + ((uint32_t)pl * PSZ + arow * SROW + acol) * 2);
                }
            uint32_t bf[4][4];
#pragma unroll
            for (int j = 0; j < 4; j++) {
                const int g  = lane >> 3;
                const int lr = lane & 7;
                const int brow = wn * 64 + j * 16 + ((g >> 1) ? 8 : 0) + lr;
                const int bcol = ks * 16 + ((g & 1) ? 8 : 0);
                ldm_x4(bf[j], bb + ((uint32_t)2 * PSZ + brow * SROW + bcol) * 2);
            }
#pragma unroll
            for (int i = 0; i < 2; i++)
#pragma unroll
                for (int j = 0; j < 8; j++)
                    mma16816(acc[i][j], af[0][i], bf[j >> 1][(j & 1) * 2],
                             bf[j >> 1][(j & 1) * 2 + 1]);
#pragma unroll
            for (int i = 0; i < 2; i++)
#pragma unroll
                for (int j = 0; j < 8; j++)
                    mma16816(acc[i][j], af[1][i], bf[j >> 1][(j & 1) * 2],
                             bf[j >> 1][(j & 1) * 2 + 1]);
#pragma unroll
            for (int j = 0; j < 4; j++) {
                const int g  = lane >> 3;
                const int lr = lane & 7;
                const int brow = wn * 64 + j * 16 + ((g >> 1) ? 8 : 0) + lr;
                const int bcol = ks * 16 + ((g & 1) ? 8 : 0);
                ldm_x4(bf[j], bb + ((uint32_t)3 * PSZ + brow * SROW + bcol) * 2);
            }
#pragma unroll
            for (int i = 0; i < 2; i++)
#pragma unroll
                for (int j = 0; j < 8; j++)
                    mma16816(acc[i][j], af[0][i], bf[j >> 1][(j & 1) * 2],
                             bf[j >> 1][(j & 1) * 2 + 1]);
        }
        __syncthreads();
    }

    // ---- epilogue ----
    const int tq = lane >> 2;
    const int tr = lane & 3;
#pragma unroll
    for (int i = 0; i < 2; i++) {
#pragma unroll
        for (int j = 0; j < 8; j++) {
#pragma unroll
            for (int half = 0; half < 2; half++) {
                const int gm = m0 + wm * 32 + i * 16 + tq + half * 8;
                if (gm >= M) continue;
#pragma unroll
                for (int e = 0; e < 2; e++) {
                    const int gn = n0 + wn * 64 + j * 8 + tr * 2 + e;
                    if (gn >= N) continue;
                    float v = acc[i][j][half * 2 + e];
                    if (mode & F_DIST) v = an2[gm] + bn2[gn] - 2.f * v;
                    if (mode & F_BIAS) v += bias[gn];
                    if (mode & F_RELU) v = fmaxf(v, 0.f);
                    const size_t o = (size_t)gm * N + gn;
                    if (mode & F_CF) Cf[o] = v;
                    if (mode & F_SP2) {
                        __nv_bfloat16 h = __float2bfloat16(v);
                        C0[o] = h;
                        C1[o] = __float2bfloat16(v - __bfloat162float(h));
                    }
                }
            }
        }
    }
}

// ---------------------------------------------------------------------------
// fp32 FFMA SGEMM (NN) — generic exact path
// ---------------------------------------------------------------------------
__global__ void __launch_bounds__(256) sgemm_nn(
    int M, int N, int K,
    const float* __restrict__ A, const float* __restrict__ Bm,
    const float* __restrict__ bias, const float* __restrict__ addsrc,
    float* __restrict__ C, int relu)
{
    __shared__ float As[8][132];
    __shared__ float Bs[8][132];
    const int t  = threadIdx.x;
    const int m0 = blockIdx.y * 128;
    const int n0 = blockIdx.x * 128;
    const int tx = t & 15, ty = t >> 4;
    const int arow = t >> 1, acol = (t & 1) * 4;
    const int brow = t >> 5, bcol = (t & 31) * 4;
    const int gm_a = m0 + arow;

    float acc[8][8];
#pragma unroll
    for (int i = 0; i < 8; i++)
#pragma unroll
        for (int j = 0; j < 8; j++) acc[i][j] = 0.f;

    for (int k0 = 0; k0 < K; k0 += 8) {
        float4 av = make_float4(0.f, 0.f, 0.f, 0.f);
        if (gm_a < M)
            av = *reinterpret_cast<const float4*>(A + (size_t)gm_a * K + k0 + acol);
        As[acol + 0][arow] = av.x; As[acol + 1][arow] = av.y;
        As[acol + 2][arow] = av.z; As[acol + 3][arow] = av.w;
        float4 bv = *reinterpret_cast<const float4*>(Bm + (size_t)(k0 + brow) * N + n0 + bcol);
        Bs[brow][bcol + 0] = bv.x; Bs[brow][bcol + 1] = bv.y;
        Bs[brow][bcol + 2] = bv.z; Bs[brow][bcol + 3] = bv.w;
        __syncthreads();
#pragma unroll
        for (int kk = 0; kk < 8; kk++) {
            float a[8], b[8];
#pragma unroll
            for (int i = 0; i < 8; i++) a[i] = As[kk][ty * 8 + i];
#pragma unroll
            for (int j = 0; j < 8; j++) b[j] = Bs[kk][tx * 8 + j];
#pragma unroll
            for (int i = 0; i < 8; i++)
#pragma unroll
                for (int j = 0; j < 8; j++)
                    acc[i][j] = fmaf(a[i], b[j], acc[i][j]);
        }
        __syncthreads();
    }
#pragma unroll
    for (int i = 0; i < 8; i++) {
        int gm = m0 + ty * 8 + i;
        if (gm >= M) continue;
#pragma unroll
        for (int j = 0; j < 8; j++) {
            int gn = n0 + tx * 8 + j;
            float v = acc[i][j];
            if (bias)   v += bias[gn];
            if (addsrc) v += addsrc[(size_t)gm * N + gn];
            if (relu)   v = fmaxf(v, 0.f);
            C[(size_t)gm * N + gn] = v;
        }
    }
}

// ---------------------------------------------------------------------------
// Projection SGEMM with fused epilogue: C fp32, bf16 h/l planes, and
// row-norm partial sums via half-warp shuffle + atomicAdd (2 partials/row,
// commutative -> deterministic).  N must be 256 (grid.x = 2).
// ---------------------------------------------------------------------------
__global__ void __launch_bounds__(256) sgemm_proj(
    int M, int K,
    const float* __restrict__ A, const float* __restrict__ Bm,
    const float* __restrict__ bias,
    float* __restrict__ C, __nv_bfloat16* __restrict__ Ph,
    __nv_bfloat16* __restrict__ Pl, float* __restrict__ nn)
{
    const int N = D;
    __shared__ float As[8][132];
    __shared__ float Bs[8][132];
    const int t  = threadIdx.x;
    const int m0 = blockIdx.y * 128;
    const int n0 = blockIdx.x * 128;
    const int tx = t & 15, ty = t >> 4;
    const int arow = t >> 1, acol = (t & 1) * 4;
    const int brow = t >> 5, bcol = (t & 31) * 4;
    const int gm_a = m0 + arow;

    float acc[8][8];
#pragma unroll
    for (int i = 0; i < 8; i++)
#pragma unroll
        for (int j = 0; j < 8; j++) acc[i][j] = 0.f;

    for (int k0 = 0; k0 < K; k0 += 8) {
        float4 av = make_float4(0.f, 0.f, 0.f, 0.f);
        if (gm_a < M)
            av = *reinterpret_cast<const float4*>(A + (size_t)gm_a * K + k0 + acol);
        As[acol + 0][arow] = av.x; As[acol + 1][arow] = av.y;
        As[acol + 2][arow] = av.z; As[acol + 3][arow] = av.w;
        float4 bv = *reinterpret_cast<const float4*>(Bm + (size_t)(k0 + brow) * N + n0 + bcol);
        Bs[brow][bcol + 0] = bv.x; Bs[brow][bcol + 1] = bv.y;
        Bs[brow][bcol + 2] = bv.z; Bs[brow][bcol + 3] = bv.w;
        __syncthreads();
#pragma unroll
        for (int kk = 0; kk < 8; kk++) {
            float a[8], b[8];
#pragma unroll
            for (int i = 0; i < 8; i++) a[i] = As[kk][ty * 8 + i];
#pragma unroll
            for (int j = 0; j < 8; j++) b[j] = Bs[kk][tx * 8 + j];
#pragma unroll
            for (int i = 0; i < 8; i++)
#pragma unroll
                for (int j = 0; j < 8; j++)
                    acc[i][j] = fmaf(a[i], b[j], acc[i][j]);
        }
        __syncthreads();
    }

#pragma unroll
    for (int i = 0; i < 8; i++) {
        const int gm = m0 + ty * 8 + i;
        const bool ok = (gm < M);
        float rowsq = 0.f;
#pragma unroll
        for (int j = 0; j < 8; j++) {
            const int gn = n0 + tx * 8 + j;
            float v = acc[i][j] + bias[gn];
            rowsq = fmaf(v, v, rowsq);
            if (ok) {
                const size_t o = (size_t)gm * N + gn;
                C[o] = v;
                __nv_bfloat16 h = __float2bfloat16(v);
                Ph[o] = h;
                Pl[o] = __float2bfloat16(v - __bfloat162float(h));
            }
        }
        // reduce across the 16 tx-lanes covering this row (no divergence)
        rowsq += __shfl_xor_sync(0xffffffffu, rowsq, 1);
        rowsq += __shfl_xor_sync(0xffffffffu, rowsq, 2);
        rowsq += __shfl_xor_sync(0xffffffffu, rowsq, 4);
        rowsq += __shfl_xor_sync(0xffffffffu, rowsq, 8);
        if (ok && tx == 0) atomicAdd(&nn[gm], rowsq);
    }
}

__global__ void zero_f(float* __restrict__ p, int n)
{
    int i = blockIdx.x * blockDim.x + threadIdx.x;
    if (i < n) p[i] = 0.f;
}

// ---------------------------------------------------------------------------
// composed bias: bc[n] = sum_k b_lin[k]*W_K[k,n] + b_K[n]
// ---------------------------------------------------------------------------
__global__ void bias_comp(const float* __restrict__ b_lin, const float* __restrict__ W_K,
                          const float* __restrict__ b_K, float* __restrict__ bc)
{
    const int n = threadIdx.x;
    float s = b_K[n];
    for (int k = 0; k < D; k++) s += b_lin[k] * W_K[k * D + n];
    bc[n] = s;
}

// W[K,N] -> transposed 2-way planes out[n*K + k]
__global__ void tsplit2(const float* __restrict__ W, int K, int N,
                        __nv_bfloat16* __restrict__ oh, __nv_bfloat16* __restrict__ ol)
{
    size_t total = (size_t)K * N;
    size_t i = (size_t)blockIdx.x * blockDim.x + threadIdx.x;
    size_t stride = (size_t)gridDim.x * blockDim.x;
    for (; i < total; i += stride) {
        int n = (int)(i / K), k = (int)(i % K);
        float v = W[(size_t)k * N + n];
        __nv_bfloat16 h = __float2bfloat16(v);
        oh[i] = h;
        ol[i] = __float2bfloat16(v - __bfloat162float(h));
    }
}

// ---------------------------------------------------------------------------
// Top-ksel smallest per row (histogram radix-select; order arbitrary)
// ---------------------------------------------------------------------------
__device__ __forceinline__ unsigned f2u(float f) {
    unsigned u = __float_as_uint(f);
    return (u & 0x80000000u) ? ~u : (u | 0x80000000u);
}

__global__ void __launch_bounds__(256) topk_kernel(
    const float* __restrict__ D2, int N, int* __restrict__ I, int ksel)
{
    const int row = blockIdx.x;
    const float* __restrict__ drow = D2 + (size_t)row * N;
    const int t = threadIdx.x;
    const unsigned target = (unsigned)(ksel - 1);

    __shared__ unsigned hist[4096];
    __shared__ unsigned bufKey[CAPK];
    __shared__ int      bufIdx[CAPK];
    __shared__ unsigned pref[256];
    __shared__ unsigned long long red[256];
    __shared__ int sh_b1, sh_b2, sh_before, sh_nOut, sh_nBuf;

    for (int i = t; i < 4096; i += 256) hist[i] = 0;
    __syncthreads();
    for (int i = t; i < N; i += 256)
        atomicAdd(&hist[f2u(drow[i]) >> 20], 1u);
    __syncthreads();

    unsigned ls = 0;
#pragma unroll
    for (int j = 0; j < 16; j++) ls += hist[t * 16 + j];
    pref[t] = ls;
    __syncthreads();
    if (t == 0) {
        unsigned run = 0;
        for (int i = 0; i < 256; i++) { unsigned s = pref[i]; pref[i] = run; run += s; }
    }
    __syncthreads();
    {
        unsigned run = pref[t];
#pragma unroll
        for (int j = 0; j < 16; j++) {
            unsigned c = hist[t * 16 + j];
            if (run <= target && target < run + c) { sh_b1 = t * 16 + j; sh_before = (int)run; }
            run += c;
        }
    }
    __syncthreads();
    const int b1 = sh_b1;
    int before = sh_before;
    const unsigned cnt_b1 = hist[b1];
    __syncthreads();

    const int use2 = (cnt_b1 > CAPK);
    int b2 = -1;
    if (use2) {
        hist[t] = 0;
        __syncthreads();
        for (int i = t; i < N; i += 256) {
            unsigned k = f2u(drow[i]);
            if ((int)(k >> 20) == b1) atomicAdd(&hist[(k >> 12) & 255u], 1u);
        }
        __syncthreads();
        if (t == 0) {
            unsigned run = 0;
            unsigned tgt = target - (unsigned)before;
            for (int i = 0; i < 256; i++) {
                unsigned c = hist[i];
                if (run <= tgt && tgt < run + c) { sh_b2 = i; sh_before = before + (int)run; break; }
                run += c;
            }
        }
        __syncthreads();
        b2 = sh_b2;
        before = sh_before;
    }

    if (t == 0) { sh_nOut = 0; sh_nBuf = 0; }
    __syncthreads();
    for (int i = t; i < N; i += 256) {
        unsigned k = f2u(drow[i]);
        unsigned hb = k >> 20;
        bool less, eq;
        if (!use2) {
            less = hb < (unsigned)b1; eq = (hb == (unsigned)b1);
        } else {
            unsigned sb = (k >> 12) & 255u;
            less = (hb < (unsigned)b1) || (hb == (unsigned)b1 && sb < (unsigned)b2);
            eq   = (hb == (unsigned)b1 && sb == (unsigned)b2);
        }
        if (less) {
            int p = atomicAdd(&sh_nOut, 1);
            if (p < ksel) I[(size_t)row * ksel + p] = i;
        } else if (eq) {
            int p = atomicAdd(&sh_nBuf, 1);
            if (p < CAPK) { bufKey[p] = k; bufIdx[p] = i; }
        }
    }
    __syncthreads();

    const int nOut = min(sh_nOut, ksel);
    const int bc   = min(sh_nBuf, CAPK);
    const int need = ksel - nOut;

    for (int it = 0; it < need; it++) {
        unsigned long long best = ~0ull;
        for (int i = t; i < bc; i += 256) {
            unsigned long long v = ((unsigned long long)bufKey[i] << 32) | (unsigned)i;
            if (v < best) best = v;
        }
        red[t] = best;
        __syncthreads();
        for (int s = 128; s > 0; s >>= 1) {
            if (t < s && red[t + s] < red[t]) red[t] = red[t + s];
            __syncthreads();
        }
        if (t == 0) {
            int p = (int)(red[0] & 0xffffffffu);
            I[(size_t)row * ksel + nOut + it] = bufIdx[p];
            bufKey[p] = 0xFFFFFFFFu;
        }
        __syncthreads();
    }
}

// ---------------------------------------------------------------------------
// Rescore: exact fp32 expanded-form d2 for KSEL preselected candidates.
// ---------------------------------------------------------------------------
__global__ void __launch_bounds__(KSEL) rescore(
    const float* __restrict__ kb, const float* __restrict__ ki,
    const float* __restrict__ kk2, const float* __restrict__ nn2,
    const int* __restrict__ I2, int* __restrict__ I)
{
    const int row = blockIdx.x, t = threadIdx.x;
    __shared__ float q[D];
    __shared__ float key[KSEL];
    q[t]       = kb[(size_t)row * D + t];
    q[t + 128] = kb[(size_t)row * D + t + 128];
    __syncthreads();
    const int idx = I2[(size_t)row * KSEL + t];
    const float4* kr = (const float4*)(ki + (size_t)idx * D);
    float dot = 0.f;
#pragma unroll 8
    for (int j = 0; j < D / 4; j++) {
        float4 v = kr[j];
        dot += q[4*j+0]*v.x + q[4*j+1]*v.y + q[4*j+2]*v.z + q[4*j+3]*v.w;
    }
    const float s = kk2[row] - 2.f * dot + nn2[idx];
    key[t] = s;
    __syncthreads();
    int rank = 0;
    for (int j = 0; j < KSEL; j++) {
        float kj = key[j];
        rank += (kj < s) || (kj == s && j < t);
    }
    if (rank < CTX) I[(size_t)row * CTX + rank] = idx;
}

// ---------------------------------------------------------------------------
// Gather: diff = k - ki (bf16 split planes), exact S, labels.
// ---------------------------------------------------------------------------
__global__ void gather_diff(
    const float* __restrict__ kq, const float* __restrict__ ki,
    const int* __restrict__ I, const int* __restrict__ cy,
    __nv_bfloat16* __restrict__ dh, __nv_bfloat16* __restrict__ dl,
    float* __restrict__ S, int* __restrict__ cls)
{
    const int bc = blockIdx.x;
    const int t  = threadIdx.x;
    const int b  = bc / CTX;
    const int idx = I[bc];
    float d = kq[(size_t)b * D + t] - ki[(size_t)idx * D + t];
    __nv_bfloat16 h = __float2bfloat16(d);
    dh[(size_t)bc * D + t] = h;
    dl[(size_t)bc * D + t] = __float2bfloat16(d - __bfloat162float(h));
    __shared__ float red[256];
    red[t] = d * d;
    __syncthreads();
    for (int k = 128; k > 0; k >>= 1) {
        if (t < k) red[t] += red[t + k];
        __syncthreads();
    }
    if (t == 0) { S[bc] = red[0]; cls[bc] = cy[idx]; }
}

__global__ void softmax96(const float* __restrict__ S, float* __restrict__ w)
{
    const int b = blockIdx.x, t = threadIdx.x;
    __shared__ float red[128];
    float v = (t < CTX) ? S[b * CTX + t] : -INFINITY;
    red[t] = v;
    __syncthreads();
    for (int k = 64; k > 0; k >>= 1) {
        if (t < k) red[t] = fmaxf(red[t], red[t + k]);
        __syncthreads();
    }
    float mx = red[0];
    __syncthreads();
    float e = (t < CTX) ? expf(v - mx) : 0.f;
    red[t] = e;
    __syncthreads();
    for (int k = 64; k > 0; k >>= 1) {
        if (t < k) red[t] += red[t + k];
        __syncthreads();
    }
    float sm = red[0];
    if (t < CTX) w[b * CTX + t] = e / sm;
}

__global__ void aggregate(
    const float* __restrict__ x, const float* __restrict__ w,
    const float* __restrict__ V, const int* __restrict__ cls,
    const float* __restrict__ Yemb, float* __restrict__ xo)
{
    const int b = blockIdx.x, t = threadIdx.x;
    float acc = x[b * D + t];
    const int base = b * CTX;
    for (int c = 0; c < CTX; c++) {
        float wv = w[base + c];
        int   cl = cls[base + c];
        acc += wv * (V[(size_t)(base + c) * D + t] + Yemb[cl * D + t]);
    }
    xo[b * D + t] = acc;
}

__global__ void ln_kernel(
    const float* __restrict__ X, const float* __restrict__ sc,
    const float* __restrict__ bi, float* __restrict__ Y)
{
    const int b = blockIdx.x, t = threadIdx.x;
    float v = X[b * D + t];
    __shared__ float red[256];
    red[t] = v;
    __syncthreads();
    for (int k = 128; k > 0; k >>= 1) { if (t < k) red[t] += red[t + k]; __syncthreads(); }
    float m = red[0] * (1.f / D);
    __syncthreads();
    float dv = v - m;
    red[t] = dv * dv;
    __syncthreads();
    for (int k = 128; k > 0; k >>= 1) { if (t < k) red[t] += red[t + k]; __syncthreads(); }
    float var = red[0] * (1.f / D);
    Y[b * D + t] = dv * rsqrtf(var + 1e-5f) * sc[t] + bi[t];
}

__global__ void head_kernel(
    const float* __restrict__ X, const float* __restrict__ sc,
    const float* __restrict__ bi, const float* __restrict__ PW,
    const float* __restrict__ Pb, float* __restrict__ out)
{
    const int b = blockIdx.x, t = threadIdx.x;
    float v = X[b * D + t];
    __shared__ float red[256];
    red[t] = v;
    __syncthreads();
    for (int k = 128; k > 0; k >>= 1) { if (t < k) red[t] += red[t + k]; __syncthreads(); }
    float m = red[0] * (1.f / D);
    __syncthreads();
    float dv = v - m;
    red[t] = dv * dv;
    __syncthreads();
    for (int k = 128; k > 0; k >>= 1) { if (t < k) red[t] += red[t + k]; __syncthreads(); }
    float var = red[0] * (1.f / D);
    __syncthreads();
    float h = fmaxf(dv * rsqrtf(var + 1e-5f) * sc[t] + bi[t], 0.f);
    for (int j = 0; j < NCLS; j++) {
        red[t] = h * PW[t * NCLS + j];
        __syncthreads();
        for (int k = 128; k > 0; k >>= 1) { if (t < k) red[t] += red[t + k]; __syncthreads(); }
        if (t == 0) out[b * NCLS + j] = red[0] + Pb[j];
        __syncthreads();
    }
}

// ---------------------------------------------------------------------------
// Launch
// ---------------------------------------------------------------------------
extern "C" void kernel_launch(void* const* d_in, const int* in_sizes, int n_in,
                              void* d_out, int out_size)
{
    (void)n_in; (void)out_size;
    const float* x_num    = (const float*)d_in[0];
    const float* cand_num = (const float*)d_in[1];
    const int*   cand_y   = (const int*)d_in[2];
    const int base = (in_sizes[3] == 1) ? 4 : 3;
    const float* W_lin   = (const float*)d_in[base + 0];
    const float* b_lin   = (const float*)d_in[base + 1];
    const float* W_K     = (const float*)d_in[base + 2];
    const float* b_K     = (const float*)d_in[base + 3];
    const float* Y_emb   = (const float*)d_in[base + 4];
    const float* T_W1    = (const float*)d_in[base + 5];
    const float* T_b1    = (const float*)d_in[base + 6];
    const float* T_W2    = (const float*)d_in[base + 7];
    const float* bp_ln_s = (const float*)d_in[base + 8];
    const float* bp_ln_b = (const float*)d_in[base + 9];
    const float* bp_W1   = (const float*)d_in[base + 10];
    const float* bp_b1   = (const float*)d_in[base + 11];
    const float* bp_W2   = (const float*)d_in[base + 12];
    const float* bp_b2   = (const float*)d_in[base + 13];
    const float* P_ln_s  = (const float*)d_in[base + 14];
    const float* P_ln_b  = (const float*)d_in[base + 15];
    const float* P_W     = (const float*)d_in[base + 16];
    const float* P_b     = (const float*)d_in[base + 17];
    float* out = (float*)d_out;

    float *Wc, *bc, *ki, *nn2, *xb, *kb, *kk2, *d2, *Vb, *xr, *lnb, *p1, *x2, *Sb, *wb;
    int *I2b, *Ib, *clsb;
    __nv_bfloat16 *kbh, *kbl, *kih, *kil, *T1h, *T1l, *T2h, *T2l, *dfh, *dfl, *mhh, *mhl;
    cudaGetSymbolAddress((void**)&Wc,  g_Wc);
    cudaGetSymbolAddress((void**)&bc,  g_bc);
    cudaGetSymbolAddress((void**)&ki,  g_ki);
    cudaGetSymbolAddress((void**)&nn2, g_nn);
    cudaGetSymbolAddress((void**)&xb,  g_x);
    cudaGetSymbolAddress((void**)&kb,  g_k);
    cudaGetSymbolAddress((void**)&kk2, g_kk);
    cudaGetSymbolAddress((void**)&d2,  g_d2);
    cudaGetSymbolAddress((void**)&Vb,  g_V);
    cudaGetSymbolAddress((void**)&xr,  g_xr);
    cudaGetSymbolAddress((void**)&lnb, g_ln);
    cudaGetSymbolAddress((void**)&p1,  g_p1);
    cudaGetSymbolAddress((void**)&x2,  g_x2);
    cudaGetSymbolAddress((void**)&Sb,  g_S);
    cudaGetSymbolAddress((void**)&wb,  g_w);
    cudaGetSymbolAddress((void**)&I2b, g_I2);
    cudaGetSymbolAddress((void**)&Ib,  g_I);
    cudaGetSymbolAddress((void**)&clsb,g_cls);
    cudaGetSymbolAddress((void**)&kbh, g_kbh); cudaGetSymbolAddress((void**)&kbl, g_kbl);
    cudaGetSymbolAddress((void**)&kih, g_kih); cudaGetSymbolAddress((void**)&kil, g_kil);
    cudaGetSymbolAddress((void**)&T1h, g_T1h); cudaGetSymbolAddress((void**)&T1l, g_T1l);
    cudaGetSymbolAddress((void**)&T2h, g_T2h); cudaGetSymbolAddress((void**)&T2l, g_T2l);
    cudaGetSymbolAddress((void**)&dfh, g_dfh); cudaGetSymbolAddress((void**)&dfl, g_dfl);
    cudaGetSymbolAddress((void**)&mhh, g_mhh); cudaGetSymbolAddress((void**)&mhl, g_mhl);

    cudaFuncSetAttribute(hmma_nt, cudaFuncAttributeMaxDynamicSharedMemorySize, SMH);

    const dim3 blk(256);

    // composed projection: W_c = W_lin@W_K, b_c = b_lin@W_K + b_K (exact fp32)
    sgemm_nn<<<dim3(D / 128, 1), blk>>>(NF, D, D, W_lin, W_K, nullptr, nullptr, Wc, 0);
    bias_comp<<<1, D>>>(b_lin, W_K, b_K, bc);

    // zero norm accumulators
    zero_f<<<(NC + 255) / 256, 256>>>(nn2, NC);
    zero_f<<<(Bq + 255) / 256, 256>>>(kk2, Bq);

    // candidate keys in ONE GEMM with fused split+norm epilogue
    sgemm_proj<<<dim3(2, (NC + 127) / 128), blk>>>(NC, NF, cand_num, Wc, bc,
                                                   ki, kih, kil, nn2);

    // query projections: xb exact, then kb with fused split+norm
    sgemm_nn<<<dim3(D / 128, Bq / 128), blk>>>(Bq, D, NF, x_num, W_lin, b_lin, nullptr, xb, 0);
    sgemm_proj<<<dim3(2, Bq / 128), blk>>>(Bq, D, xb, W_K, b_K, kb, kbh, kbl, kk2);

    // weight planes for T-MLP
    tsplit2<<<256, 256>>>(T_W1, D,  DI, T1h, T1l);
    tsplit2<<<256, 256>>>(T_W2, DI, D,  T2h, T2l);

    // tensor-core distance (approx, L2-friendly order) -> top-128 -> rescore
    hmma_nt<<<dim3(Bq / 128, (NC + 127) / 128), blk, SMH>>>(
        Bq, NC, D, kbh, kbl, kih, kil, nullptr, kk2, nn2, d2, nullptr, nullptr,
        F_DIST | F_CF, 1);
    topk_kernel<<<Bq, 256>>>(d2, NC, I2b, KSEL);
    rescore<<<Bq, KSEL>>>(kb, ki, kk2, nn2, I2b, Ib);

    // gather (exact S + diff splits) + softmax
    gather_diff<<<Bq * CTX, 256>>>(kb, ki, Ib, cand_y, dfh, dfl, Sb, clsb);
    softmax96<<<Bq, 128>>>(Sb, wb);

    // tensor-core T-MLP
    hmma_nt<<<dim3(DI / 128, BCTX / 128), blk, SMH>>>(
        BCTX, DI, D, dfh, dfl, T1h, T1l, T_b1, nullptr, nullptr,
        nullptr, mhh, mhl, F_BIAS | F_RELU | F_SP2, 0);
    hmma_nt<<<dim3(D / 128, BCTX / 128), blk, SMH>>>(
        BCTX, D, DI, mhh, mhl, T2h, T2l, nullptr, nullptr, nullptr,
        Vb, nullptr, nullptr, F_CF, 0);

    // aggregation + predictor + head (exact fp32)
    aggregate<<<Bq, 256>>>(xb, wb, Vb, clsb, Y_emb, xr);
    ln_kernel<<<Bq, 256>>>(xr, bp_ln_s, bp_ln_b, lnb);
    sgemm_nn<<<dim3(DI / 128, Bq / 128), blk>>>(Bq, DI, D,  lnb, bp_W1, bp_b1, nullptr, p1, 1);
    sgemm_nn<<<dim3(D / 128,  Bq / 128), blk>>>(Bq, D,  DI, p1,  bp_W2, bp_b2, xr,      x2, 0);
    head_kernel<<<Bq, 256>>>(x2, P_ln_s, P_ln_b, P_W, P_b, out);
}

// round 16
// speedup vs baseline: 1.0597x; 1.0597x over previous
#include <cuda_runtime.h>
#include <cuda_bf16.h>
#include <cuda_fp16.h>
#include <math.h>
#include <stdint.h>

#define Bq    1024
#define NF    128
#define D     256
#define DI    512
#define NC    100000
#define CTX   96
#define KSEL  128
#define NCLS  10
#define CAPK  3584
#define BCTX  (Bq * CTX)

// ---------------------------------------------------------------------------
// Device scratch
// ---------------------------------------------------------------------------
__device__ float  g_Wc [NF * D];          // composed W_lin @ W_K
__device__ float  g_bc [D];               // composed bias
__device__ float  g_ki [(size_t)NC * D];
__device__ float  g_nn [NC];
__device__ float  g_x  [Bq * D];
__device__ float  g_k  [Bq * D];
__device__ float  g_kk [Bq];
__device__ __half g_d2 [(size_t)Bq * NC];         // fp16 approx distances (preselect only)
__device__ float  g_V  [(size_t)BCTX * D];
__device__ float  g_xr [Bq * D];
__device__ float  g_ln [Bq * D];
__device__ float  g_p1 [Bq * DI];
__device__ float  g_x2 [Bq * D];
__device__ float  g_S  [Bq * CTX];
__device__ float  g_w  [Bq * CTX];
__device__ int    g_I2 [Bq * KSEL];
__device__ int    g_I  [Bq * CTX];
__device__ int    g_cls[Bq * CTX];
// bf16 split planes (h = bf16(x), l = bf16(x - h))
__device__ __nv_bfloat16 g_kbh[Bq * D],            g_kbl[Bq * D];
__device__ __nv_bfloat16 g_kih[(size_t)NC * D],    g_kil[(size_t)NC * D];
__device__ __nv_bfloat16 g_T1h[(size_t)DI * D],    g_T1l[(size_t)DI * D];
__device__ __nv_bfloat16 g_T2h[(size_t)D * DI],    g_T2l[(size_t)D * DI];
__device__ __nv_bfloat16 g_dfh[(size_t)BCTX * D],  g_dfl[(size_t)BCTX * D];
__device__ __nv_bfloat16 g_mhh[(size_t)BCTX * DI], g_mhl[(size_t)BCTX * DI];

// ---------------------------------------------------------------------------
// Warp MMA / cp.async helpers (baseline PTX, sm_80+)
// ---------------------------------------------------------------------------
__device__ __forceinline__ uint32_t smem_u32(const void* p) {
    uint32_t a;
    asm("{ .reg .u64 t; cvta.to.shared.u64 t, %1; cvt.u32.u64 %0, t; }" : "=r"(a) : "l"(p));
    return a;
}
__device__ __forceinline__ void ldm_x4(uint32_t* r, uint32_t addr) {
    asm volatile("ldmatrix.sync.aligned.m8n8.x4.shared.b16 {%0,%1,%2,%3}, [%4];"
                 : "=r"(r[0]), "=r"(r[1]), "=r"(r[2]), "=r"(r[3]) : "r"(addr));
}
__device__ __forceinline__ void mma16816(float* c, const uint32_t* a, uint32_t b0, uint32_t b1) {
    asm volatile(
        "mma.sync.aligned.m16n8k16.row.col.f32.bf16.bf16.f32 "
        "{%0,%1,%2,%3}, {%4,%5,%6,%7}, {%8,%9}, {%0,%1,%2,%3};"
        : "+f"(c[0]), "+f"(c[1]), "+f"(c[2]), "+f"(c[3])
        : "r"(a[0]), "r"(a[1]), "r"(a[2]), "r"(a[3]), "r"(b0), "r"(b1));
}
__device__ __forceinline__ void cp16(uint32_t saddr, const void* g, bool pred) {
    int sz = pred ? 16 : 0;
    asm volatile("cp.async.cg.shared.global [%0], [%1], 16, %2;"
                 :: "r"(saddr), "l"(g), "r"(sz));
}
#define CP_COMMIT() asm volatile("cp.async.commit_group;" ::: "memory")

// mode flags
#define F_CF    1
#define F_SP2   2
#define F_RELU  8
#define F_BIAS  16
#define F_DIST  32
#define F_CF16  64   // write Cf as __half (reinterpret Cf pointer)

#define SROW 40     // smem row stride in halves (80B, 16B-aligned)
#define PSZ  (128 * SROW)       // one plane tile in halves
#define SMH  (2 * 4 * PSZ * 2)  // bytes: 2 bufs x 4 planes = 81920

// ---------------------------------------------------------------------------
// Split-bf16 NT GEMM, cp.async double-buffered, fragment-cached.
// C[m,n] ~= A0*B0 + A0*B1 + A1*B0 (2-plane, 3-product; rel err ~1.5e-5).
// Tile 128x128, BK=32, 256 threads (8 warps: 4M x 2N of 32x64).
// __launch_bounds__(256,2): cap regs at 128 so 2 CTAs/SM are resident
// (2 x 80KB smem = 160KB <= 228KB) for cross-CTA latency hiding.
// ---------------------------------------------------------------------------
__global__ void __launch_bounds__(256, 2) hmma_nt(
    int M, int N, int K,
    const __nv_bfloat16* __restrict__ A0, const __nv_bfloat16* __restrict__ A1,
    const __nv_bfloat16* __restrict__ B0, const __nv_bfloat16* __restrict__ B1,
    const float* __restrict__ bias, const float* __restrict__ an2,
    const float* __restrict__ bn2,
    float* __restrict__ Cf, __nv_bfloat16* __restrict__ C0,
    __nv_bfloat16* __restrict__ C1, int mode)
{
    extern __shared__ __align__(16) __nv_bfloat16 sm[];

    const int t    = threadIdx.x;
    const int lane = t & 31;
    const int wid  = t >> 5;
    const int wm   = wid & 3;
    const int wn   = wid >> 2;
    const int m0   = blockIdx.y * 128;
    const int n0   = blockIdx.x * 128;

    float acc[2][8][4];
#pragma unroll
    for (int i = 0; i < 2; i++)
#pragma unroll
        for (int j = 0; j < 8; j++)
#pragma unroll
            for (int r = 0; r < 4; r++) acc[i][j][r] = 0.f;

    const __nv_bfloat16* G[4] = {A0, A1, B0, B1};
    const uint32_t sbase = smem_u32(sm);

    const int l_row = t >> 1;
    const int l_q0  = (t & 1) * 2;
    auto issue = [&](int ch, int buf) {
        const int k0 = ch << 5;
        const uint32_t bofs = (uint32_t)buf * 4 * PSZ * 2;
#pragma unroll
        for (int pl = 0; pl < 4; pl++) {
            const bool isA = (pl < 2);
            const int  grow = (isA ? m0 : n0) + l_row;
            const bool ok   = isA ? (grow < M) : (grow < N);
            const __nv_bfloat16* src = G[pl] + (size_t)grow * K + k0 + l_q0 * 8;
            const uint32_t dst = sbase + bofs +
                ((uint32_t)pl * PSZ + (uint32_t)l_row * SROW + l_q0 * 8) * 2;
            cp16(dst,     src,     ok);
            cp16(dst + 16, src + 8, ok);
        }
        CP_COMMIT();
    };

    const int nchunk = K >> 5;
    issue(0, 0);

    for (int ch = 0; ch < nchunk; ch++) {
        const int buf  = ch & 1;
        const bool more = (ch + 1 < nchunk);
        if (more) issue(ch + 1, buf ^ 1);
        if (more) asm volatile("cp.async.wait_group 1;" ::: "memory");
        else      asm volatile("cp.async.wait_group 0;" ::: "memory");
        __syncthreads();

        const uint32_t bb = sbase + (uint32_t)buf * 4 * PSZ * 2;
#pragma unroll
        for (int ks = 0; ks < 2; ks++) {
            uint32_t af[2][2][4];
#pragma unroll
            for (int pl = 0; pl < 2; pl++)
#pragma unroll
                for (int i = 0; i < 2; i++) {
                    const int arow = wm * 32 + i * 16 + (lane & 15);
                    const int acol = ks * 16 + (lane >> 4) * 8;
                    ldm_x4(af[pl][i],
                           bb + ((uint32_t)pl * PSZ + arow * SROW + acol) * 2);
                }
            uint32_t bf[4][4];
#pragma unroll
            for (int j = 0; j < 4; j++) {
                const int g  = lane >> 3;
                const int lr = lane & 7;
                const int brow = wn * 64 + j * 16 + ((g >> 1) ? 8 : 0) + lr;
                const int bcol = ks * 16 + ((g & 1) ? 8 : 0);
                ldm_x4(bf[j], bb + ((uint32_t)2 * PSZ + brow * SROW + bcol) * 2);
            }
#pragma unroll
            for (int i = 0; i < 2; i++)
#pragma unroll
                for (int j = 0; j < 8; j++)
                    mma16816(acc[i][j], af[0][i], bf[j >> 1][(j & 1) * 2],
                             bf[j >> 1][(j & 1) * 2 + 1]);
#pragma unroll
            for (int i = 0; i < 2; i++)
#pragma unroll
                for (int j = 0; j < 8; j++)
                    mma16816(acc[i][j], af[1][i], bf[j >> 1][(j & 1) * 2],
                             bf[j >> 1][(j & 1) * 2 + 1]);
#pragma unroll
            for (int j = 0; j < 4; j++) {
                const int g  = lane >> 3;
                const int lr = lane & 7;
                const int brow = wn * 64 + j * 16 + ((g >> 1) ? 8 : 0) + lr;
                const int bcol = ks * 16 + ((g & 1) ? 8 : 0);
                ldm_x4(bf[j], bb + ((uint32_t)3 * PSZ + brow * SROW + bcol) * 2);
            }
#pragma unroll
            for (int i = 0; i < 2; i++)
#pragma unroll
                for (int j = 0; j < 8; j++)
                    mma16816(acc[i][j], af[0][i], bf[j >> 1][(j & 1) * 2],
                             bf[j >> 1][(j & 1) * 2 + 1]);
        }
        __syncthreads();
    }

    // ---- epilogue ----
    const int tq = lane >> 2;
    const int tr = lane & 3;
#pragma unroll
    for (int i = 0; i < 2; i++) {
#pragma unroll
        for (int j = 0; j < 8; j++) {
#pragma unroll
            for (int half = 0; half < 2; half++) {
                const int gm = m0 + wm * 32 + i * 16 + tq + half * 8;
                if (gm >= M) continue;
#pragma unroll
                for (int e = 0; e < 2; e++) {
                    const int gn = n0 + wn * 64 + j * 8 + tr * 2 + e;
                    if (gn >= N) continue;
                    float v = acc[i][j][half * 2 + e];
                    if (mode & F_DIST) v = an2[gm] + bn2[gn] - 2.f * v;
                    if (mode & F_BIAS) v += bias[gn];
                    if (mode & F_RELU) v = fmaxf(v, 0.f);
                    const size_t o = (size_t)gm * N + gn;
                    if (mode & F_CF)   Cf[o] = v;
                    if (mode & F_CF16)
                        reinterpret_cast<__half*>(Cf)[o] = __float2half_rn(v);
                    if (mode & F_SP2) {
                        __nv_bfloat16 h = __float2bfloat16(v);
                        C0[o] = h;
                        C1[o] = __float2bfloat16(v - __bfloat162float(h));
                    }
                }
            }
        }
    }
}

// ---------------------------------------------------------------------------
// fp32 FFMA SGEMM (NN) — exact path for projections / predictor
// ---------------------------------------------------------------------------
__global__ void __launch_bounds__(256) sgemm_nn(
    int M, int N, int K,
    const float* __restrict__ A, const float* __restrict__ Bm,
    const float* __restrict__ bias, const float* __restrict__ addsrc,
    float* __restrict__ C, int relu)
{
    __shared__ float As[8][132];
    __shared__ float Bs[8][132];
    const int t  = threadIdx.x;
    const int m0 = blockIdx.y * 128;
    const int n0 = blockIdx.x * 128;
    const int tx = t & 15, ty = t >> 4;
    const int arow = t >> 1, acol = (t & 1) * 4;
    const int brow = t >> 5, bcol = (t & 31) * 4;
    const int gm_a = m0 + arow;

    float acc[8][8];
#pragma unroll
    for (int i = 0; i < 8; i++)
#pragma unroll
        for (int j = 0; j < 8; j++) acc[i][j] = 0.f;

    for (int k0 = 0; k0 < K; k0 += 8) {
        float4 av = make_float4(0.f, 0.f, 0.f, 0.f);
        if (gm_a < M)
            av = *reinterpret_cast<const float4*>(A + (size_t)gm_a * K + k0 + acol);
        As[acol + 0][arow] = av.x; As[acol + 1][arow] = av.y;
        As[acol + 2][arow] = av.z; As[acol + 3][arow] = av.w;
        float4 bv = *reinterpret_cast<const float4*>(Bm + (size_t)(k0 + brow) * N + n0 + bcol);
        Bs[brow][bcol + 0] = bv.x; Bs[brow][bcol + 1] = bv.y;
        Bs[brow][bcol + 2] = bv.z; Bs[brow][bcol + 3] = bv.w;
        __syncthreads();
#pragma unroll
        for (int kk = 0; kk < 8; kk++) {
            float a[8], b[8];
#pragma unroll
            for (int i = 0; i < 8; i++) a[i] = As[kk][ty * 8 + i];
#pragma unroll
            for (int j = 0; j < 8; j++) b[j] = Bs[kk][tx * 8 + j];
#pragma unroll
            for (int i = 0; i < 8; i++)
#pragma unroll
                for (int j = 0; j < 8; j++)
                    acc[i][j] = fmaf(a[i], b[j], acc[i][j]);
        }
        __syncthreads();
    }
#pragma unroll
    for (int i = 0; i < 8; i++) {
        int gm = m0 + ty * 8 + i;
        if (gm >= M) continue;
#pragma unroll
        for (int j = 0; j < 8; j++) {
            int gn = n0 + tx * 8 + j;
            float v = acc[i][j];
            if (bias)   v += bias[gn];
            if (addsrc) v += addsrc[(size_t)gm * N + gn];
            if (relu)   v = fmaxf(v, 0.f);
            C[(size_t)gm * N + gn] = v;
        }
    }
}

// ---------------------------------------------------------------------------
// composed bias: bc[n] = sum_k b_lin[k]*W_K[k,n] + b_K[n]
// ---------------------------------------------------------------------------
__global__ void bias_comp(const float* __restrict__ b_lin, const float* __restrict__ W_K,
                          const float* __restrict__ b_K, float* __restrict__ bc)
{
    const int n = threadIdx.x;
    float s = b_K[n];
    for (int k = 0; k < D; k++) s += b_lin[k] * W_K[k * D + n];
    bc[n] = s;
}

// ---------------------------------------------------------------------------
// Fused split + row norm: one pass over X[r, 0..D)
// ---------------------------------------------------------------------------
__global__ void split_norm(const float* __restrict__ X,
                           __nv_bfloat16* __restrict__ h,
                           __nv_bfloat16* __restrict__ l,
                           float* __restrict__ nn)
{
    const int r = blockIdx.x, t = threadIdx.x;
    const size_t o = (size_t)r * D + t;
    float v = X[o];
    __nv_bfloat16 vh = __float2bfloat16(v);
    h[o] = vh;
    l[o] = __float2bfloat16(v - __bfloat162float(vh));
    __shared__ float red[256];
    red[t] = v * v;
    __syncthreads();
    for (int k = 128; k > 0; k >>= 1) {
        if (t < k) red[t] += red[t + k];
        __syncthreads();
    }
    if (t == 0) nn[r] = red[0];
}

// W[K,N] -> transposed 2-way planes out[n*K + k]
__global__ void tsplit2(const float* __restrict__ W, int K, int N,
                        __nv_bfloat16* __restrict__ oh, __nv_bfloat16* __restrict__ ol)
{
    size_t total = (size_t)K * N;
    size_t i = (size_t)blockIdx.x * blockDim.x + threadIdx.x;
    size_t stride = (size_t)gridDim.x * blockDim.x;
    for (; i < total; i += stride) {
        int n = (int)(i / K), k = (int)(i % K);
        float v = W[(size_t)k * N + n];
        __nv_bfloat16 h = __float2bfloat16(v);
        oh[i] = h;
        ol[i] = __float2bfloat16(v - __bfloat162float(h));
    }
}

// ---------------------------------------------------------------------------
// Top-ksel smallest per row over fp16 keys (histogram radix-select)
// ---------------------------------------------------------------------------
__device__ __forceinline__ unsigned f2u(float f) {
    unsigned u = __float_as_uint(f);
    return (u & 0x80000000u) ? ~u : (u | 0x80000000u);
}

__global__ void __launch_bounds__(256) topk_kernel(
    const __half* __restrict__ D2, int N, int* __restrict__ I, int ksel)
{
    const int row = blockIdx.x;
    const __half* __restrict__ drow = D2 + (size_t)row * N;
    const int t = threadIdx.x;
    const unsigned target = (unsigned)(ksel - 1);

    __shared__ unsigned hist[4096];
    __shared__ unsigned bufKey[CAPK];
    __shared__ int      bufIdx[CAPK];
    __shared__ unsigned pref[256];
    __shared__ unsigned long long red[256];
    __shared__ int sh_b1, sh_b2, sh_before, sh_nOut, sh_nBuf;

    for (int i = t; i < 4096; i += 256) hist[i] = 0;
    __syncthreads();
    for (int i = t; i < N; i += 256)
        atomicAdd(&hist[f2u(__half2float(drow[i])) >> 20], 1u);
    __syncthreads();

    unsigned ls = 0;
#pragma unroll
    for (int j = 0; j < 16; j++) ls += hist[t * 16 + j];
    pref[t] = ls;
    __syncthreads();
    if (t == 0) {
        unsigned run = 0;
        for (int i = 0; i < 256; i++) { unsigned s = pref[i]; pref[i] = run; run += s; }
    }
    __syncthreads();
    {
        unsigned run = pref[t];
#pragma unroll
        for (int j = 0; j < 16; j++) {
            unsigned c = hist[t * 16 + j];
            if (run <= target && target < run + c) { sh_b1 = t * 16 + j; sh_before = (int)run; }
            run += c;
        }
    }
    __syncthreads();
    const int b1 = sh_b1;
    int before = sh_before;
    const unsigned cnt_b1 = hist[b1];
    __syncthreads();

    const int use2 = (cnt_b1 > CAPK);
    int b2 = -1;
    if (use2) {
        hist[t] = 0;
        __syncthreads();
        for (int i = t; i < N; i += 256) {
            unsigned k = f2u(__half2float(drow[i]));
            if ((int)(k >> 20) == b1) atomicAdd(&hist[(k >> 12) & 255u], 1u);
        }
        __syncthreads();
        if (t == 0) {
            unsigned run = 0;
            unsigned tgt = target - (unsigned)before;
            for (int i = 0; i < 256; i++) {
                unsigned c = hist[i];
                if (run <= tgt && tgt < run + c) { sh_b2 = i; sh_before = before + (int)run; break; }
                run += c;
            }
        }
        __syncthreads();
        b2 = sh_b2;
        before = sh_before;
    }

    if (t == 0) { sh_nOut = 0; sh_nBuf = 0; }
    __syncthreads();
    for (int i = t; i < N; i += 256) {
        unsigned k = f2u(__half2float(drow[i]));
        unsigned hb = k >> 20;
        bool less, eq;
        if (!use2) {
            less = hb < (unsigned)b1; eq = (hb == (unsigned)b1);
        } else {
            unsigned sb = (k >> 12) & 255u;
            less = (hb < (unsigned)b1) || (hb == (unsigned)b1 && sb < (unsigned)b2);
            eq   = (hb == (unsigned)b1 && sb == (unsigned)b2);
        }
        if (less) {
            int p = atomicAdd(&sh_nOut, 1);
            if (p < ksel) I[(size_t)row * ksel + p] = i;
        } else if (eq) {
            int p = atomicAdd(&sh_nBuf, 1);
            if (p < CAPK) { bufKey[p] = k; bufIdx[p] = i; }
        }
    }
    __syncthreads();

    const int nOut = min(sh_nOut, ksel);
    const int bc   = min(sh_nBuf, CAPK);
    const int need = ksel - nOut;

    for (int it = 0; it < need; it++) {
        unsigned long long best = ~0ull;
        for (int i = t; i < bc; i += 256) {
            unsigned long long v = ((unsigned long long)bufKey[i] << 32) | (unsigned)i;
            if (v < best) best = v;
        }
        red[t] = best;
        __syncthreads();
        for (int s = 128; s > 0; s >>= 1) {
            if (t < s && red[t + s] < red[t]) red[t] = red[t + s];
            __syncthreads();
        }
        if (t == 0) {
            int p = (int)(red[0] & 0xffffffffu);
            I[(size_t)row * ksel + nOut + it] = bufIdx[p];
            bufKey[p] = 0xFFFFFFFFu;
        }
        __syncthreads();
    }
}

// ---------------------------------------------------------------------------
// Rescore: exact fp32 expanded-form d2 for KSEL preselected candidates.
// ---------------------------------------------------------------------------
__global__ void __launch_bounds__(KSEL) rescore(
    const float* __restrict__ kb, const float* __restrict__ ki,
    const float* __restrict__ kk2, const float* __restrict__ nn2,
    const int* __restrict__ I2, int* __restrict__ I)
{
    const int row = blockIdx.x, t = threadIdx.x;
    __shared__ float q[D];
    __shared__ float key[KSEL];
    q[t]       = kb[(size_t)row * D + t];
    q[t + 128] = kb[(size_t)row * D + t + 128];
    __syncthreads();
    const int idx = I2[(size_t)row * KSEL + t];
    const float4* kr = (const float4*)(ki + (size_t)idx * D);
    float dot = 0.f;
#pragma unroll 8
    for (int j = 0; j < D / 4; j++) {
        float4 v = kr[j];
        dot += q[4*j+0]*v.x + q[4*j+1]*v.y + q[4*j+2]*v.z + q[4*j+3]*v.w;
    }
    const float s = kk2[row] - 2.f * dot + nn2[idx];
    key[t] = s;
    __syncthreads();
    int rank = 0;
    for (int j = 0; j < KSEL; j++) {
        float kj = key[j];
        rank += (kj < s) || (kj == s && j < t);
    }
    if (rank < CTX) I[(size_t)row * CTX + rank] = idx;
}

// ---------------------------------------------------------------------------
// Gather: diff = k - ki (bf16 split planes), exact S, labels.
// ---------------------------------------------------------------------------
__global__ void gather_diff(
    const float* __restrict__ kq, const float* __restrict__ ki,
    const int* __restrict__ I, const int* __restrict__ cy,
    __nv_bfloat16* __restrict__ dh, __nv_bfloat16* __restrict__ dl,
    float* __restrict__ S, int* __restrict__ cls)
{
    const int bc = blockIdx.x;
    const int t  = threadIdx.x;
    const int b  = bc / CTX;
    const int idx = I[bc];
    float d = kq[(size_t)b * D + t] - ki[(size_t)idx * D + t];
    __nv_bfloat16 h = __float2bfloat16(d);
    dh[(size_t)bc * D + t] = h;
    dl[(size_t)bc * D + t] = __float2bfloat16(d - __bfloat162float(h));
    __shared__ float red[256];
    red[t] = d * d;
    __syncthreads();
    for (int k = 128; k > 0; k >>= 1) {
        if (t < k) red[t] += red[t + k];
        __syncthreads();
    }
    if (t == 0) { S[bc] = red[0]; cls[bc] = cy[idx]; }
}

__global__ void softmax96(const float* __restrict__ S, float* __restrict__ w)
{
    const int b = blockIdx.x, t = threadIdx.x;
    __shared__ float red[128];
    float v = (t < CTX) ? S[b * CTX + t] : -INFINITY;
    red[t] = v;
    __syncthreads();
    for (int k = 64; k > 0; k >>= 1) {
        if (t < k) red[t] = fmaxf(red[t], red[t + k]);
        __syncthreads();
    }
    float mx = red[0];
    __syncthreads();
    float e = (t < CTX) ? expf(v - mx) : 0.f;
    red[t] = e;
    __syncthreads();
    for (int k = 64; k > 0; k >>= 1) {
        if (t < k) red[t] += red[t + k];
        __syncthreads();
    }
    float sm = red[0];
    if (t < CTX) w[b * CTX + t] = e / sm;
}

__global__ void aggregate(
    const float* __restrict__ x, const float* __restrict__ w,
    const float* __restrict__ V, const int* __restrict__ cls,
    const float* __restrict__ Yemb, float* __restrict__ xo)
{
    const int b = blockIdx.x, t = threadIdx.x;
    float acc = x[b * D + t];
    const int base = b * CTX;
    for (int c = 0; c < CTX; c++) {
        float wv = w[base + c];
        int   cl = cls[base + c];
        acc += wv * (V[(size_t)(base + c) * D + t] + Yemb[cl * D + t]);
    }
    xo[b * D + t] = acc;
}

__global__ void ln_kernel(
    const float* __restrict__ X, const float* __restrict__ sc,
    const float* __restrict__ bi, float* __restrict__ Y)
{
    const int b = blockIdx.x, t = threadIdx.x;
    float v = X[b * D + t];
    __shared__ float red[256];
    red[t] = v;
    __syncthreads();
    for (int k = 128; k > 0; k >>= 1) { if (t < k) red[t] += red[t + k]; __syncthreads(); }
    float m = red[0] * (1.f / D);
    __syncthreads();
    float dv = v - m;
    red[t] = dv * dv;
    __syncthreads();
    for (int k = 128; k > 0; k >>= 1) { if (t < k) red[t] += red[t + k]; __syncthreads(); }
    float var = red[0] * (1.f / D);
    Y[b * D + t] = dv * rsqrtf(var + 1e-5f) * sc[t] + bi[t];
}

__global__ void head_kernel(
    const float* __restrict__ X, const float* __restrict__ sc,
    const float* __restrict__ bi, const float* __restrict__ PW,
    const float* __restrict__ Pb, float* __restrict__ out)
{
    const int b = blockIdx.x, t = threadIdx.x;
    float v = X[b * D + t];
    __shared__ float red[256];
    red[t] = v;
    __syncthreads();
    for (int k = 128; k > 0; k >>= 1) { if (t < k) red[t] += red[t + k]; __syncthreads(); }
    float m = red[0] * (1.f / D);
    __syncthreads();
    float dv = v - m;
    red[t] = dv * dv;
    __syncthreads();
    for (int k = 128; k > 0; k >>= 1) { if (t < k) red[t] += red[t + k]; __syncthreads(); }
    float var = red[0] * (1.f / D);
    __syncthreads();
    float h = fmaxf(dv * rsqrtf(var + 1e-5f) * sc[t] + bi[t], 0.f);
    for (int j = 0; j < NCLS; j++) {
        red[t] = h * PW[t * NCLS + j];
        __syncthreads();
        for (int k = 128; k > 0; k >>= 1) { if (t < k) red[t] += red[t + k]; __syncthreads(); }
        if (t == 0) out[b * NCLS + j] = red[0] + Pb[j];
        __syncthreads();
    }
}

// ---------------------------------------------------------------------------
// Launch
// ---------------------------------------------------------------------------
extern "C" void kernel_launch(void* const* d_in, const int* in_sizes, int n_in,
                              void* d_out, int out_size)
{
    (void)n_in; (void)out_size;
    const float* x_num    = (const float*)d_in[0];
    const float* cand_num = (const float*)d_in[1];
    const int*   cand_y   = (const int*)d_in[2];
    const int base = (in_sizes[3] == 1) ? 4 : 3;
    const float* W_lin   = (const float*)d_in[base + 0];
    const float* b_lin   = (const float*)d_in[base + 1];
    const float* W_K     = (const float*)d_in[base + 2];
    const float* b_K     = (const float*)d_in[base + 3];
    const float* Y_emb   = (const float*)d_in[base + 4];
    const float* T_W1    = (const float*)d_in[base + 5];
    const float* T_b1    = (const float*)d_in[base + 6];
    const float* T_W2    = (const float*)d_in[base + 7];
    const float* bp_ln_s = (const float*)d_in[base + 8];
    const float* bp_ln_b = (const float*)d_in[base + 9];
    const float* bp_W1   = (const float*)d_in[base + 10];
    const float* bp_b1   = (const float*)d_in[base + 11];
    const float* bp_W2   = (const float*)d_in[base + 12];
    const float* bp_b2   = (const float*)d_in[base + 13];
    const float* P_ln_s  = (const float*)d_in[base + 14];
    const float* P_ln_b  = (const float*)d_in[base + 15];
    const float* P_W     = (const float*)d_in[base + 16];
    const float* P_b     = (const float*)d_in[base + 17];
    float* out = (float*)d_out;

    float *Wc, *bc, *ki, *nn2, *xb, *kb, *kk2, *Vb, *xr, *lnb, *p1, *x2, *Sb, *wb;
    __half *d2;
    int *I2b, *Ib, *clsb;
    __nv_bfloat16 *kbh, *kbl, *kih, *kil, *T1h, *T1l, *T2h, *T2l, *dfh, *dfl, *mhh, *mhl;
    cudaGetSymbolAddress((void**)&Wc,  g_Wc);
    cudaGetSymbolAddress((void**)&bc,  g_bc);
    cudaGetSymbolAddress((void**)&ki,  g_ki);
    cudaGetSymbolAddress((void**)&nn2, g_nn);
    cudaGetSymbolAddress((void**)&xb,  g_x);
    cudaGetSymbolAddress((void**)&kb,  g_k);
    cudaGetSymbolAddress((void**)&kk2, g_kk);
    cudaGetSymbolAddress((void**)&d2,  g_d2);
    cudaGetSymbolAddress((void**)&Vb,  g_V);
    cudaGetSymbolAddress((void**)&xr,  g_xr);
    cudaGetSymbolAddress((void**)&lnb, g_ln);
    cudaGetSymbolAddress((void**)&p1,  g_p1);
    cudaGetSymbolAddress((void**)&x2,  g_x2);
    cudaGetSymbolAddress((void**)&Sb,  g_S);
    cudaGetSymbolAddress((void**)&wb,  g_w);
    cudaGetSymbolAddress((void**)&I2b, g_I2);
    cudaGetSymbolAddress((void**)&Ib,  g_I);
    cudaGetSymbolAddress((void**)&clsb,g_cls);
    cudaGetSymbolAddress((void**)&kbh, g_kbh); cudaGetSymbolAddress((void**)&kbl, g_kbl);
    cudaGetSymbolAddress((void**)&kih, g_kih); cudaGetSymbolAddress((void**)&kil, g_kil);
    cudaGetSymbolAddress((void**)&T1h, g_T1h); cudaGetSymbolAddress((void**)&T1l, g_T1l);
    cudaGetSymbolAddress((void**)&T2h, g_T2h); cudaGetSymbolAddress((void**)&T2l, g_T2l);
    cudaGetSymbolAddress((void**)&dfh, g_dfh); cudaGetSymbolAddress((void**)&dfl, g_dfl);
    cudaGetSymbolAddress((void**)&mhh, g_mhh); cudaGetSymbolAddress((void**)&mhl, g_mhl);

    cudaFuncSetAttribute(hmma_nt, cudaFuncAttributeMaxDynamicSharedMemorySize, SMH);

    const dim3 blk(256);

    // composed projection: W_c = W_lin@W_K, b_c = b_lin@W_K + b_K (exact fp32)
    sgemm_nn<<<dim3(D / 128, 1), blk>>>(NF, D, D, W_lin, W_K, nullptr, nullptr, Wc, 0);
    bias_comp<<<1, D>>>(b_lin, W_K, b_K, bc);

    // candidate keys in ONE GEMM: ki = cand @ W_c + b_c
    sgemm_nn<<<dim3(D / 128, (NC + 127) / 128), blk>>>(NC, D, NF, cand_num, Wc, bc, nullptr, ki, 0);

    // query projections (two-stage: x needed for residual)
    sgemm_nn<<<dim3(D / 128, Bq / 128), blk>>>(Bq, D, NF, x_num, W_lin, b_lin, nullptr, xb, 0);
    sgemm_nn<<<dim3(D / 128, Bq / 128), blk>>>(Bq, D, D,  xb,    W_K,   b_K,   nullptr, kb, 0);

    // fused split+norm (single pass over ki / kb)
    split_norm<<<NC, 256>>>(ki, kih, kil, nn2);
    split_norm<<<Bq, 256>>>(kb, kbh, kbl, kk2);
    tsplit2<<<256, 256>>>(T_W1, D,  DI, T1h, T1l);
    tsplit2<<<256, 256>>>(T_W2, DI, D,  T2h, T2l);

    // tensor-core distance (approx, fp16 output) -> top-128 -> exact rescore
    hmma_nt<<<dim3((NC + 127) / 128, Bq / 128), blk, SMH>>>(
        Bq, NC, D, kbh, kbl, kih, kil, nullptr, kk2, nn2,
        reinterpret_cast<float*>(d2), nullptr, nullptr, F_DIST | F_CF16);
    topk_kernel<<<Bq, 256>>>(d2, NC, I2b, KSEL);
    rescore<<<Bq, KSEL>>>(kb, ki, kk2, nn2, I2b, Ib);

    // gather (exact S + diff splits) + softmax
    gather_diff<<<Bq * CTX, 256>>>(kb, ki, Ib, cand_y, dfh, dfl, Sb, clsb);
    softmax96<<<Bq, 128>>>(Sb, wb);

    // tensor-core T-MLP
    hmma_nt<<<dim3(DI / 128, BCTX / 128), blk, SMH>>>(
        BCTX, DI, D, dfh, dfl, T1h, T1l, T_b1, nullptr, nullptr,
        nullptr, mhh, mhl, F_BIAS | F_RELU | F_SP2);
    hmma_nt<<<dim3(D / 128, BCTX / 128), blk, SMH>>>(
        BCTX, D, DI, mhh, mhl, T2h, T2l, nullptr, nullptr, nullptr,
        Vb, nullptr, nullptr, F_CF);

    // aggregation + predictor + head (exact fp32)
    aggregate<<<Bq, 256>>>(xb, wb, Vb, clsb, Y_emb, xr);
    ln_kernel<<<Bq, 256>>>(xr, bp_ln_s, bp_ln_b, lnb);
    sgemm_nn<<<dim3(DI / 128, Bq / 128), blk>>>(Bq, DI, D,  lnb, bp_W1, bp_b1, nullptr, p1, 1);
    sgemm_nn<<<dim3(D / 128,  Bq / 128), blk>>>(Bq, D,  DI, p1,  bp_W2, bp_b2, xr,      x2, 0);
    head_kernel<<<Bq, 256>>>(x2, P_ln_s, P_ln_b, P_W, P_b, out);
}

// round 17
// speedup vs baseline: 1.1769x; 1.1106x over previous
#include <cuda_runtime.h>
#include <cuda_bf16.h>
#include <cuda_fp16.h>
#include <math.h>
#include <stdint.h>

#define Bq    1024
#define NF    128
#define D     256
#define DI    512
#define NC    100000
#define CTX   96
#define KSEL  128
#define NCLS  10
#define CAPK  3584
#define BCTX  (Bq * CTX)

// ---------------------------------------------------------------------------
// Device scratch
// ---------------------------------------------------------------------------
__device__ float  g_Wc [NF * D];
__device__ float  g_bc [D];
__device__ float  g_ki [(size_t)NC * D];
__device__ float  g_nn [NC];
__device__ float  g_x  [Bq * D];
__device__ float  g_k  [Bq * D];
__device__ float  g_kk [Bq];
__device__ __half g_d2 [(size_t)Bq * NC];
__device__ float  g_V  [(size_t)BCTX * D];
__device__ float  g_xr [Bq * D];
__device__ float  g_ln [Bq * D];
__device__ float  g_p1 [Bq * DI];
__device__ float  g_x2 [Bq * D];
__device__ float  g_S  [Bq * CTX];
__device__ float  g_w  [Bq * CTX];
__device__ int    g_I2 [Bq * KSEL];
__device__ int    g_I  [Bq * CTX];
__device__ int    g_cls[Bq * CTX];
// fp16 single planes for the preselect distance GEMM
__device__ __half g_kbf[Bq * D];
__device__ __half g_kif[(size_t)NC * D];
// bf16 split planes (T-MLP path)
__device__ __nv_bfloat16 g_T1h[(size_t)DI * D],    g_T1l[(size_t)DI * D];
__device__ __nv_bfloat16 g_T2h[(size_t)D * DI],    g_T2l[(size_t)D * DI];
__device__ __nv_bfloat16 g_dfh[(size_t)BCTX * D],  g_dfl[(size_t)BCTX * D];
__device__ __nv_bfloat16 g_mhh[(size_t)BCTX * DI], g_mhl[(size_t)BCTX * DI];

// ---------------------------------------------------------------------------
// Warp MMA / cp.async helpers (baseline PTX, sm_80+)
// ---------------------------------------------------------------------------
__device__ __forceinline__ uint32_t smem_u32(const void* p) {
    uint32_t a;
    asm("{ .reg .u64 t; cvta.to.shared.u64 t, %1; cvt.u32.u64 %0, t; }" : "=r"(a) : "l"(p));
    return a;
}
__device__ __forceinline__ void ldm_x4(uint32_t* r, uint32_t addr) {
    asm volatile("ldmatrix.sync.aligned.m8n8.x4.shared.b16 {%0,%1,%2,%3}, [%4];"
                 : "=r"(r[0]), "=r"(r[1]), "=r"(r[2]), "=r"(r[3]) : "r"(addr));
}
__device__ __forceinline__ void mma16816(float* c, const uint32_t* a, uint32_t b0, uint32_t b1) {
    asm volatile(
        "mma.sync.aligned.m16n8k16.row.col.f32.bf16.bf16.f32 "
        "{%0,%1,%2,%3}, {%4,%5,%6,%7}, {%8,%9}, {%0,%1,%2,%3};"
        : "+f"(c[0]), "+f"(c[1]), "+f"(c[2]), "+f"(c[3])
        : "r"(a[0]), "r"(a[1]), "r"(a[2]), "r"(a[3]), "r"(b0), "r"(b1));
}
__device__ __forceinline__ void mma16816h(float* c, const uint32_t* a, uint32_t b0, uint32_t b1) {
    asm volatile(
        "mma.sync.aligned.m16n8k16.row.col.f32.f16.f16.f32 "
        "{%0,%1,%2,%3}, {%4,%5,%6,%7}, {%8,%9}, {%0,%1,%2,%3};"
        : "+f"(c[0]), "+f"(c[1]), "+f"(c[2]), "+f"(c[3])
        : "r"(a[0]), "r"(a[1]), "r"(a[2]), "r"(a[3]), "r"(b0), "r"(b1));
}
__device__ __forceinline__ void cp16(uint32_t saddr, const void* g, bool pred) {
    int sz = pred ? 16 : 0;
    asm volatile("cp.async.cg.shared.global [%0], [%1], 16, %2;"
                 :: "r"(saddr), "l"(g), "r"(sz));
}
#define CP_COMMIT() asm volatile("cp.async.commit_group;" ::: "memory")

// mode flags
#define F_CF    1
#define F_SP2   2
#define F_RELU  8
#define F_BIAS  16

#define SROW 40                  // smem row stride in halves (80B)
#define PSZ  (128 * SROW)        // one plane tile in halves
#define SMH  (2 * 4 * PSZ * 2)   // hmma_nt: 2 bufs x 4 planes = 81920 B
#define SMHD (2 * 2 * PSZ * 2)   // hmma_dist: 2 bufs x 2 planes = 40960 B

// ---------------------------------------------------------------------------
// Split-bf16 NT GEMM (T-MLP path), cp.async double-buffered, 3 products.
// Tile 128x128, BK=32, 256 threads (8 warps: 4M x 2N of 32x64).
// ---------------------------------------------------------------------------
__global__ void __launch_bounds__(256, 2) hmma_nt(
    int M, int N, int K,
    const __nv_bfloat16* __restrict__ A0, const __nv_bfloat16* __restrict__ A1,
    const __nv_bfloat16* __restrict__ B0, const __nv_bfloat16* __restrict__ B1,
    const float* __restrict__ bias,
    float* __restrict__ Cf, __nv_bfloat16* __restrict__ C0,
    __nv_bfloat16* __restrict__ C1, int mode)
{
    extern __shared__ __align__(16) __nv_bfloat16 sm[];

    const int t    = threadIdx.x;
    const int lane = t & 31;
    const int wid  = t >> 5;
    const int wm   = wid & 3;
    const int wn   = wid >> 2;
    const int m0   = blockIdx.y * 128;
    const int n0   = blockIdx.x * 128;

    float acc[2][8][4];
#pragma unroll
    for (int i = 0; i < 2; i++)
#pragma unroll
        for (int j = 0; j < 8; j++)
#pragma unroll
            for (int r = 0; r < 4; r++) acc[i][j][r] = 0.f;

    const __nv_bfloat16* G[4] = {A0, A1, B0, B1};
    const uint32_t sbase = smem_u32(sm);

    const int l_row = t >> 1;
    const int l_q0  = (t & 1) * 2;
    auto issue = [&](int ch, int buf) {
        const int k0 = ch << 5;
        const uint32_t bofs = (uint32_t)buf * 4 * PSZ * 2;
#pragma unroll
        for (int pl = 0; pl < 4; pl++) {
            const bool isA = (pl < 2);
            const int  grow = (isA ? m0 : n0) + l_row;
            const bool ok   = isA ? (grow < M) : (grow < N);
            const __nv_bfloat16* src = G[pl] + (size_t)grow * K + k0 + l_q0 * 8;
            const uint32_t dst = sbase + bofs +
                ((uint32_t)pl * PSZ + (uint32_t)l_row * SROW + l_q0 * 8) * 2;
            cp16(dst,      src,     ok);
            cp16(dst + 16, src + 8, ok);
        }
        CP_COMMIT();
    };

    const int nchunk = K >> 5;
    issue(0, 0);

    for (int ch = 0; ch < nchunk; ch++) {
        const int buf  = ch & 1;
        const bool more = (ch + 1 < nchunk);
        if (more) issue(ch + 1, buf ^ 1);
        if (more) asm volatile("cp.async.wait_group 1;" ::: "memory");
        else      asm volatile("cp.async.wait_group 0;" ::: "memory");
        __syncthreads();

        const uint32_t bb = sbase + (uint32_t)buf * 4 * PSZ * 2;
#pragma unroll
        for (int ks = 0; ks < 2; ks++) {
            uint32_t af[2][2][4];
#pragma unroll
            for (int pl = 0; pl < 2; pl++)
#pragma unroll
                for (int i = 0; i < 2; i++) {
                    const int arow = wm * 32 + i * 16 + (lane & 15);
                    const int acol = ks * 16 + (lane >> 4) * 8;
                    ldm_x4(af[pl][i],
                           bb + ((uint32_t)pl * PSZ + arow * SROW + acol) * 2);
                }
            uint32_t bf[4][4];
#pragma unroll
            for (int j = 0; j < 4; j++) {
                const int g  = lane >> 3;
                const int lr = lane & 7;
                const int brow = wn * 64 + j * 16 + ((g >> 1) ? 8 : 0) + lr;
                const int bcol = ks * 16 + ((g & 1) ? 8 : 0);
                ldm_x4(bf[j], bb + ((uint32_t)2 * PSZ + brow * SROW + bcol) * 2);
            }
#pragma unroll
            for (int i = 0; i < 2; i++)
#pragma unroll
                for (int j = 0; j < 8; j++)
                    mma16816(acc[i][j], af[0][i], bf[j >> 1][(j & 1) * 2],
                             bf[j >> 1][(j & 1) * 2 + 1]);
#pragma unroll
            for (int i = 0; i < 2; i++)
#pragma unroll
                for (int j = 0; j < 8; j++)
                    mma16816(acc[i][j], af[1][i], bf[j >> 1][(j & 1) * 2],
                             bf[j >> 1][(j & 1) * 2 + 1]);
#pragma unroll
            for (int j = 0; j < 4; j++) {
                const int g  = lane >> 3;
                const int lr = lane & 7;
                const int brow = wn * 64 + j * 16 + ((g >> 1) ? 8 : 0) + lr;
                const int bcol = ks * 16 + ((g & 1) ? 8 : 0);
                ldm_x4(bf[j], bb + ((uint32_t)3 * PSZ + brow * SROW + bcol) * 2);
            }
#pragma unroll
            for (int i = 0; i < 2; i++)
#pragma unroll
                for (int j = 0; j < 8; j++)
                    mma16816(acc[i][j], af[0][i], bf[j >> 1][(j & 1) * 2],
                             bf[j >> 1][(j & 1) * 2 + 1]);
        }
        __syncthreads();
    }

    // ---- epilogue ----
    const int tq = lane >> 2;
    const int tr = lane & 3;
#pragma unroll
    for (int i = 0; i < 2; i++) {
#pragma unroll
        for (int j = 0; j < 8; j++) {
#pragma unroll
            for (int half = 0; half < 2; half++) {
                const int gm = m0 + wm * 32 + i * 16 + tq + half * 8;
                if (gm >= M) continue;
#pragma unroll
                for (int e = 0; e < 2; e++) {
                    const int gn = n0 + wn * 64 + j * 8 + tr * 2 + e;
                    if (gn >= N) continue;
                    float v = acc[i][j][half * 2 + e];
                    if (mode & F_BIAS) v += bias[gn];
                    if (mode & F_RELU) v = fmaxf(v, 0.f);
                    const size_t o = (size_t)gm * N + gn;
                    if (mode & F_CF)   Cf[o] = v;
                    if (mode & F_SP2) {
                        __nv_bfloat16 h = __float2bfloat16(v);
                        C0[o] = h;
                        C1[o] = __float2bfloat16(v - __bfloat162float(h));
                    }
                }
            }
        }
    }
}

// ---------------------------------------------------------------------------
// fp16 single-plane distance GEMM (preselect only):
// Cd[m,n] = fp16(an2[m] + bn2[n] - 2 * sum_k A[m,k]*B[n,k])
// Error ~0.2 absolute vs rank-96->128 gap ~70: exact top-96 preserved in
// top-KSEL with ~50x margin; exact fp32 rescore finalizes selection.
// Tile 128x128, BK=32, 2 plane-tiles/chunk (A,B), 1 product, 16 mma/ks.
// ---------------------------------------------------------------------------
__global__ void __launch_bounds__(256, 2) hmma_dist_f16(
    int M, int N, int K,
    const __half* __restrict__ A, const __half* __restrict__ B,
    const float* __restrict__ an2, const float* __restrict__ bn2,
    __half* __restrict__ Cd)
{
    extern __shared__ __align__(16) __half smh[];

    const int t    = threadIdx.x;
    const int lane = t & 31;
    const int wid  = t >> 5;
    const int wm   = wid & 3;
    const int wn   = wid >> 2;
    const int m0   = blockIdx.y * 128;
    const int n0   = blockIdx.x * 128;

    float acc[2][8][4];
#pragma unroll
    for (int i = 0; i < 2; i++)
#pragma unroll
        for (int j = 0; j < 8; j++)
#pragma unroll
            for (int r = 0; r < 4; r++) acc[i][j][r] = 0.f;

    const uint32_t sbase = smem_u32(smh);
    const int l_row = t >> 1;
    const int l_q0  = (t & 1) * 2;
    auto issue = [&](int ch, int buf) {
        const int k0 = ch << 5;
        const uint32_t bofs = (uint32_t)buf * 2 * PSZ * 2;
#pragma unroll
        for (int pl = 0; pl < 2; pl++) {
            const __half* base = pl ? B : A;
            const int  grow = (pl ? n0 : m0) + l_row;
            const bool ok   = pl ? (grow < N) : (grow < M);
            const __half* src = base + (size_t)grow * K + k0 + l_q0 * 8;
            const uint32_t dst = sbase + bofs +
                ((uint32_t)pl * PSZ + (uint32_t)l_row * SROW + l_q0 * 8) * 2;
            cp16(dst,      src,     ok);
            cp16(dst + 16, src + 8, ok);
        }
        CP_COMMIT();
    };

    const int nchunk = K >> 5;
    issue(0, 0);

    for (int ch = 0; ch < nchunk; ch++) {
        const int buf  = ch & 1;
        const bool more = (ch + 1 < nchunk);
        if (more) issue(ch + 1, buf ^ 1);
        if (more) asm volatile("cp.async.wait_group 1;" ::: "memory");
        else      asm volatile("cp.async.wait_group 0;" ::: "memory");
        __syncthreads();

        const uint32_t bb = sbase + (uint32_t)buf * 2 * PSZ * 2;
#pragma unroll
        for (int ks = 0; ks < 2; ks++) {
            uint32_t af[2][4];
#pragma unroll
            for (int i = 0; i < 2; i++) {
                const int arow = wm * 32 + i * 16 + (lane & 15);
                const int acol = ks * 16 + (lane >> 4) * 8;
                ldm_x4(af[i], bb + ((uint32_t)(arow * SROW + acol)) * 2);
            }
            uint32_t bf[4][4];
#pragma unroll
            for (int j = 0; j < 4; j++) {
                const int g  = lane >> 3;
                const int lr = lane & 7;
                const int brow = wn * 64 + j * 16 + ((g >> 1) ? 8 : 0) + lr;
                const int bcol = ks * 16 + ((g & 1) ? 8 : 0);
                ldm_x4(bf[j], bb + ((uint32_t)PSZ + brow * SROW + bcol) * 2);
            }
#pragma unroll
            for (int i = 0; i < 2; i++)
#pragma unroll
                for (int j = 0; j < 8; j++)
                    mma16816h(acc[i][j], af[i], bf[j >> 1][(j & 1) * 2],
                              bf[j >> 1][(j & 1) * 2 + 1]);
        }
        __syncthreads();
    }

    const int tq = lane >> 2;
    const int tr = lane & 3;
#pragma unroll
    for (int i = 0; i < 2; i++) {
#pragma unroll
        for (int j = 0; j < 8; j++) {
#pragma unroll
            for (int half = 0; half < 2; half++) {
                const int gm = m0 + wm * 32 + i * 16 + tq + half * 8;
                if (gm >= M) continue;
                const float a2 = an2[gm];
#pragma unroll
                for (int e = 0; e < 2; e++) {
                    const int gn = n0 + wn * 64 + j * 8 + tr * 2 + e;
                    if (gn >= N) continue;
                    const float v = a2 + bn2[gn] - 2.f * acc[i][j][half * 2 + e];
                    Cd[(size_t)gm * N + gn] = __float2half_rn(v);
                }
            }
        }
    }
}

// ---------------------------------------------------------------------------
// fp32 FFMA SGEMM (NN) — exact path for projections / predictor
// ---------------------------------------------------------------------------
__global__ void __launch_bounds__(256) sgemm_nn(
    int M, int N, int K,
    const float* __restrict__ A, const float* __restrict__ Bm,
    const float* __restrict__ bias, const float* __restrict__ addsrc,
    float* __restrict__ C, int relu)
{
    __shared__ float As[8][132];
    __shared__ float Bs[8][132];
    const int t  = threadIdx.x;
    const int m0 = blockIdx.y * 128;
    const int n0 = blockIdx.x * 128;
    const int tx = t & 15, ty = t >> 4;
    const int arow = t >> 1, acol = (t & 1) * 4;
    const int brow = t >> 5, bcol = (t & 31) * 4;
    const int gm_a = m0 + arow;

    float acc[8][8];
#pragma unroll
    for (int i = 0; i < 8; i++)
#pragma unroll
        for (int j = 0; j < 8; j++) acc[i][j] = 0.f;

    for (int k0 = 0; k0 < K; k0 += 8) {
        float4 av = make_float4(0.f, 0.f, 0.f, 0.f);
        if (gm_a < M)
            av = *reinterpret_cast<const float4*>(A + (size_t)gm_a * K + k0 + acol);
        As[acol + 0][arow] = av.x; As[acol + 1][arow] = av.y;
        As[acol + 2][arow] = av.z; As[acol + 3][arow] = av.w;
        float4 bv = *reinterpret_cast<const float4*>(Bm + (size_t)(k0 + brow) * N + n0 + bcol);
        Bs[brow][bcol + 0] = bv.x; Bs[brow][bcol + 1] = bv.y;
        Bs[brow][bcol + 2] = bv.z; Bs[brow][bcol + 3] = bv.w;
        __syncthreads();
#pragma unroll
        for (int kk = 0; kk < 8; kk++) {
            float a[8], b[8];
#pragma unroll
            for (int i = 0; i < 8; i++) a[i] = As[kk][ty * 8 + i];
#pragma unroll
            for (int j = 0; j < 8; j++) b[j] = Bs[kk][tx * 8 + j];
#pragma unroll
            for (int i = 0; i < 8; i++)
#pragma unroll
                for (int j = 0; j < 8; j++)
                    acc[i][j] = fmaf(a[i], b[j], acc[i][j]);
        }
        __syncthreads();
    }
#pragma unroll
    for (int i = 0; i < 8; i++) {
        int gm = m0 + ty * 8 + i;
        if (gm >= M) continue;
#pragma unroll
        for (int j = 0; j < 8; j++) {
            int gn = n0 + tx * 8 + j;
            float v = acc[i][j];
            if (bias)   v += bias[gn];
            if (addsrc) v += addsrc[(size_t)gm * N + gn];
            if (relu)   v = fmaxf(v, 0.f);
            C[(size_t)gm * N + gn] = v;
        }
    }
}

// ---------------------------------------------------------------------------
// composed bias: bc[n] = sum_k b_lin[k]*W_K[k,n] + b_K[n]
// ---------------------------------------------------------------------------
__global__ void bias_comp(const float* __restrict__ b_lin, const float* __restrict__ W_K,
                          const float* __restrict__ b_K, float* __restrict__ bc)
{
    const int n = threadIdx.x;
    float s = b_K[n];
    for (int k = 0; k < D; k++) s += b_lin[k] * W_K[k * D + n];
    bc[n] = s;
}

// ---------------------------------------------------------------------------
// Fused fp16-plane + row norm: one pass over X[r, 0..D)
// ---------------------------------------------------------------------------
__global__ void split_norm_f16(const float* __restrict__ X,
                               __half* __restrict__ h,
                               float* __restrict__ nn)
{
    const int r = blockIdx.x, t = threadIdx.x;
    const size_t o = (size_t)r * D + t;
    float v = X[o];
    h[o] = __float2half_rn(v);
    __shared__ float red[256];
    red[t] = v * v;
    __syncthreads();
    for (int k = 128; k > 0; k >>= 1) {
        if (t < k) red[t] += red[t + k];
        __syncthreads();
    }
    if (t == 0) nn[r] = red[0];
}

// W[K,N] -> transposed 2-way bf16 planes out[n*K + k]
__global__ void tsplit2(const float* __restrict__ W, int K, int N,
                        __nv_bfloat16* __restrict__ oh, __nv_bfloat16* __restrict__ ol)
{
    size_t total = (size_t)K * N;
    size_t i = (size_t)blockIdx.x * blockDim.x + threadIdx.x;
    size_t stride = (size_t)gridDim.x * blockDim.x;
    for (; i < total; i += stride) {
        int n = (int)(i / K), k = (int)(i % K);
        float v = W[(size_t)k * N + n];
        __nv_bfloat16 h = __float2bfloat16(v);
        oh[i] = h;
        ol[i] = __float2bfloat16(v - __bfloat162float(h));
    }
}

// ---------------------------------------------------------------------------
// Top-ksel smallest per row over fp16 keys (histogram radix-select)
// ---------------------------------------------------------------------------
__device__ __forceinline__ unsigned f2u(float f) {
    unsigned u = __float_as_uint(f);
    return (u & 0x80000000u) ? ~u : (u | 0x80000000u);
}

__global__ void __launch_bounds__(256) topk_kernel(
    const __half* __restrict__ D2, int N, int* __restrict__ I, int ksel)
{
    const int row = blockIdx.x;
    const __half* __restrict__ drow = D2 + (size_t)row * N;
    const int t = threadIdx.x;
    const unsigned target = (unsigned)(ksel - 1);

    __shared__ unsigned hist[4096];
    __shared__ unsigned bufKey[CAPK];
    __shared__ int      bufIdx[CAPK];
    __shared__ unsigned pref[256];
    __shared__ unsigned long long red[256];
    __shared__ int sh_b1, sh_b2, sh_before, sh_nOut, sh_nBuf;

    for (int i = t; i < 4096; i += 256) hist[i] = 0;
    __syncthreads();
    for (int i = t; i < N; i += 256)
        atomicAdd(&hist[f2u(__half2float(drow[i])) >> 20], 1u);
    __syncthreads();

    unsigned ls = 0;
#pragma unroll
    for (int j = 0; j < 16; j++) ls += hist[t * 16 + j];
    pref[t] = ls;
    __syncthreads();
    if (t == 0) {
        unsigned run = 0;
        for (int i = 0; i < 256; i++) { unsigned s = pref[i]; pref[i] = run; run += s; }
    }
    __syncthreads();
    {
        unsigned run = pref[t];
#pragma unroll
        for (int j = 0; j < 16; j++) {
            unsigned c = hist[t * 16 + j];
            if (run <= target && target < run + c) { sh_b1 = t * 16 + j; sh_before = (int)run; }
            run += c;
        }
    }
    __syncthreads();
    const int b1 = sh_b1;
    int before = sh_before;
    const unsigned cnt_b1 = hist[b1];
    __syncthreads();

    const int use2 = (cnt_b1 > CAPK);
    int b2 = -1;
    if (use2) {
        hist[t] = 0;
        __syncthreads();
        for (int i = t; i < N; i += 256) {
            unsigned k = f2u(__half2float(drow[i]));
            if ((int)(k >> 20) == b1) atomicAdd(&hist[(k >> 12) & 255u], 1u);
        }
        __syncthreads();
        if (t == 0) {
            unsigned run = 0;
            unsigned tgt = target - (unsigned)before;
            for (int i = 0; i < 256; i++) {
                unsigned c = hist[i];
                if (run <= tgt && tgt < run + c) { sh_b2 = i; sh_before = before + (int)run; break; }
                run += c;
            }
        }
        __syncthreads();
        b2 = sh_b2;
        before = sh_before;
    }

    if (t == 0) { sh_nOut = 0; sh_nBuf = 0; }
    __syncthreads();
    for (int i = t; i < N; i += 256) {
        unsigned k = f2u(__half2float(drow[i]));
        unsigned hb = k >> 20;
        bool less, eq;
        if (!use2) {
            less = hb < (unsigned)b1; eq = (hb == (unsigned)b1);
        } else {
            unsigned sb = (k >> 12) & 255u;
            less = (hb < (unsigned)b1) || (hb == (unsigned)b1 && sb < (unsigned)b2);
            eq   = (hb == (unsigned)b1 && sb == (unsigned)b2);
        }
        if (less) {
            int p = atomicAdd(&sh_nOut, 1);
            if (p < ksel) I[(size_t)row * ksel + p] = i;
        } else if (eq) {
            int p = atomicAdd(&sh_nBuf, 1);
            if (p < CAPK) { bufKey[p] = k; bufIdx[p] = i; }
        }
    }
    __syncthreads();

    const int nOut = min(sh_nOut, ksel);
    const int bc   = min(sh_nBuf, CAPK);
    const int need = ksel - nOut;

    for (int it = 0; it < need; it++) {
        unsigned long long best = ~0ull;
        for (int i = t; i < bc; i += 256) {
            unsigned long long v = ((unsigned long long)bufKey[i] << 32) | (unsigned)i;
            if (v < best) best = v;
        }
        red[t] = best;
        __syncthreads();
        for (int s = 128; s > 0; s >>= 1) {
            if (t < s && red[t + s] < red[t]) red[t] = red[t + s];
            __syncthreads();
        }
        if (t == 0) {
            int p = (int)(red[0] & 0xffffffffu);
            I[(size_t)row * ksel + nOut + it] = bufIdx[p];
            bufKey[p] = 0xFFFFFFFFu;
        }
        __syncthreads();
    }
}

// ---------------------------------------------------------------------------
// Rescore: exact fp32 expanded-form d2 for KSEL preselected candidates.
// ---------------------------------------------------------------------------
__global__ void __launch_bounds__(KSEL) rescore(
    const float* __restrict__ kb, const float* __restrict__ ki,
    const float* __restrict__ kk2, const float* __restrict__ nn2,
    const int* __restrict__ I2, int* __restrict__ I)
{
    const int row = blockIdx.x, t = threadIdx.x;
    __shared__ float q[D];
    __shared__ float key[KSEL];
    q[t]       = kb[(size_t)row * D + t];
    q[t + 128] = kb[(size_t)row * D + t + 128];
    __syncthreads();
    const int idx = I2[(size_t)row * KSEL + t];
    const float4* kr = (const float4*)(ki + (size_t)idx * D);
    float dot = 0.f;
#pragma unroll 8
    for (int j = 0; j < D / 4; j++) {
        float4 v = kr[j];
        dot += q[4*j+0]*v.x + q[4*j+1]*v.y + q[4*j+2]*v.z + q[4*j+3]*v.w;
    }
    const float s = kk2[row] - 2.f * dot + nn2[idx];
    key[t] = s;
    __syncthreads();
    int rank = 0;
    for (int j = 0; j < KSEL; j++) {
        float kj = key[j];
        rank += (kj < s) || (kj == s && j < t);
    }
    if (rank < CTX) I[(size_t)row * CTX + rank] = idx;
}

// ---------------------------------------------------------------------------
// Gather: diff = k - ki (bf16 split planes), exact S, labels.
// ---------------------------------------------------------------------------
__global__ void gather_diff(
    const float* __restrict__ kq, const float* __restrict__ ki,
    const int* __restrict__ I, const int* __restrict__ cy,
    __nv_bfloat16* __restrict__ dh, __nv_bfloat16* __restrict__ dl,
    float* __restrict__ S, int* __restrict__ cls)
{
    const int bc = blockIdx.x;
    const int t  = threadIdx.x;
    const int b  = bc / CTX;
    const int idx = I[bc];
    float d = kq[(size_t)b * D + t] - ki[(size_t)idx * D + t];
    __nv_bfloat16 h = __float2bfloat16(d);
    dh[(size_t)bc * D + t] = h;
    dl[(size_t)bc * D + t] = __float2bfloat16(d - __bfloat162float(h));
    __shared__ float red[256];
    red[t] = d * d;
    __syncthreads();
    for (int k = 128; k > 0; k >>= 1) {
        if (t < k) red[t] += red[t + k];
        __syncthreads();
    }
    if (t == 0) { S[bc] = red[0]; cls[bc] = cy[idx]; }
}

__global__ void softmax96(const float* __restrict__ S, float* __restrict__ w)
{
    const int b = blockIdx.x, t = threadIdx.x;
    __shared__ float red[128];
    float v = (t < CTX) ? S[b * CTX + t] : -INFINITY;
    red[t] = v;
    __syncthreads();
    for (int k = 64; k > 0; k >>= 1) {
        if (t < k) red[t] = fmaxf(red[t], red[t + k]);
        __syncthreads();
    }
    float mx = red[0];
    __syncthreads();
    float e = (t < CTX) ? expf(v - mx) : 0.f;
    red[t] = e;
    __syncthreads();
    for (int k = 64; k > 0; k >>= 1) {
        if (t < k) red[t] += red[t + k];
        __syncthreads();
    }
    float sm = red[0];
    if (t < CTX) w[b * CTX + t] = e / sm;
}

__global__ void aggregate(
    const float* __restrict__ x, const float* __restrict__ w,
    const float* __restrict__ V, const int* __restrict__ cls,
    const float* __restrict__ Yemb, float* __restrict__ xo)
{
    const int b = blockIdx.x, t = threadIdx.x;
    float acc = x[b * D + t];
    const int base = b * CTX;
    for (int c = 0; c < CTX; c++) {
        float wv = w[base + c];
        int   cl = cls[base + c];
        acc += wv * (V[(size_t)(base + c) * D + t] + Yemb[cl * D + t]);
    }
    xo[b * D + t] = acc;
}

__global__ void ln_kernel(
    const float* __restrict__ X, const float* __restrict__ sc,
    const float* __restrict__ bi, float* __restrict__ Y)
{
    const int b = blockIdx.x, t = threadIdx.x;
    float v = X[b * D + t];
    __shared__ float red[256];
    red[t] = v;
    __syncthreads();
    for (int k = 128; k > 0; k >>= 1) { if (t < k) red[t] += red[t + k]; __syncthreads(); }
    float m = red[0] * (1.f / D);
    __syncthreads();
    float dv = v - m;
    red[t] = dv * dv;
    __syncthreads();
    for (int k = 128; k > 0; k >>= 1) { if (t < k) red[t] += red[t + k]; __syncthreads(); }
    float var = red[0] * (1.f / D);
    Y[b * D + t] = dv * rsqrtf(var + 1e-5f) * sc[t] + bi[t];
}

__global__ void head_kernel(
    const float* __restrict__ X, const float* __restrict__ sc,
    const float* __restrict__ bi, const float* __restrict__ PW,
    const float* __restrict__ Pb, float* __restrict__ out)
{
    const int b = blockIdx.x, t = threadIdx.x;
    float v = X[b * D + t];
    __shared__ float red[256];
    red[t] = v;
    __syncthreads();
    for (int k = 128; k > 0; k >>= 1) { if (t < k) red[t] += red[t + k]; __syncthreads(); }
    float m = red[0] * (1.f / D);
    __syncthreads();
    float dv = v - m;
    red[t] = dv * dv;
    __syncthreads();
    for (int k = 128; k > 0; k >>= 1) { if (t < k) red[t] += red[t + k]; __syncthreads(); }
    float var = red[0] * (1.f / D);
    __syncthreads();
    float h = fmaxf(dv * rsqrtf(var + 1e-5f) * sc[t] + bi[t], 0.f);
    for (int j = 0; j < NCLS; j++) {
        red[t] = h * PW[t * NCLS + j];
        __syncthreads();
        for (int k = 128; k > 0; k >>= 1) { if (t < k) red[t] += red[t + k]; __syncthreads(); }
        if (t == 0) out[b * NCLS + j] = red[0] + Pb[j];
        __syncthreads();
    }
}

// ---------------------------------------------------------------------------
// Launch
// ---------------------------------------------------------------------------
extern "C" void kernel_launch(void* const* d_in, const int* in_sizes, int n_in,
                              void* d_out, int out_size)
{
    (void)n_in; (void)out_size;
    const float* x_num    = (const float*)d_in[0];
    const float* cand_num = (const float*)d_in[1];
    const int*   cand_y   = (const int*)d_in[2];
    const int base = (in_sizes[3] == 1) ? 4 : 3;
    const float* W_lin   = (const float*)d_in[base + 0];
    const float* b_lin   = (const float*)d_in[base + 1];
    const float* W_K     = (const float*)d_in[base + 2];
    const float* b_K     = (const float*)d_in[base + 3];
    const float* Y_emb   = (const float*)d_in[base + 4];
    const float* T_W1    = (const float*)d_in[base + 5];
    const float* T_b1    = (const float*)d_in[base + 6];
    const float* T_W2    = (const float*)d_in[base + 7];
    const float* bp_ln_s = (const float*)d_in[base + 8];
    const float* bp_ln_b = (const float*)d_in[base + 9];
    const float* bp_W1   = (const float*)d_in[base + 10];
    const float* bp_b1   = (const float*)d_in[base + 11];
    const float* bp_W2   = (const float*)d_in[base + 12];
    const float* bp_b2   = (const float*)d_in[base + 13];
    const float* P_ln_s  = (const float*)d_in[base + 14];
    const float* P_ln_b  = (const float*)d_in[base + 15];
    const float* P_W     = (const float*)d_in[base + 16];
    const float* P_b     = (const float*)d_in[base + 17];
    float* out = (float*)d_out;

    float *Wc, *bc, *ki, *nn2, *xb, *kb, *kk2, *Vb, *xr, *lnb, *p1, *x2, *Sb, *wb;
    __half *d2, *kbf, *kif;
    int *I2b, *Ib, *clsb;
    __nv_bfloat16 *T1h, *T1l, *T2h, *T2l, *dfh, *dfl, *mhh, *mhl;
    cudaGetSymbolAddress((void**)&Wc,  g_Wc);
    cudaGetSymbolAddress((void**)&bc,  g_bc);
    cudaGetSymbolAddress((void**)&ki,  g_ki);
    cudaGetSymbolAddress((void**)&nn2, g_nn);
    cudaGetSymbolAddress((void**)&xb,  g_x);
    cudaGetSymbolAddress((void**)&kb,  g_k);
    cudaGetSymbolAddress((void**)&kk2, g_kk);
    cudaGetSymbolAddress((void**)&d2,  g_d2);
    cudaGetSymbolAddress((void**)&Vb,  g_V);
    cudaGetSymbolAddress((void**)&xr,  g_xr);
    cudaGetSymbolAddress((void**)&lnb, g_ln);
    cudaGetSymbolAddress((void**)&p1,  g_p1);
    cudaGetSymbolAddress((void**)&x2,  g_x2);
    cudaGetSymbolAddress((void**)&Sb,  g_S);
    cudaGetSymbolAddress((void**)&wb,  g_w);
    cudaGetSymbolAddress((void**)&I2b, g_I2);
    cudaGetSymbolAddress((void**)&Ib,  g_I);
    cudaGetSymbolAddress((void**)&clsb,g_cls);
    cudaGetSymbolAddress((void**)&kbf, g_kbf);
    cudaGetSymbolAddress((void**)&kif, g_kif);
    cudaGetSymbolAddress((void**)&T1h, g_T1h); cudaGetSymbolAddress((void**)&T1l, g_T1l);
    cudaGetSymbolAddress((void**)&T2h, g_T2h); cudaGetSymbolAddress((void**)&T2l, g_T2l);
    cudaGetSymbolAddress((void**)&dfh, g_dfh); cudaGetSymbolAddress((void**)&dfl, g_dfl);
    cudaGetSymbolAddress((void**)&mhh, g_mhh); cudaGetSymbolAddress((void**)&mhl, g_mhl);

    cudaFuncSetAttribute(hmma_nt, cudaFuncAttributeMaxDynamicSharedMemorySize, SMH);
    cudaFuncSetAttribute(hmma_dist_f16, cudaFuncAttributeMaxDynamicSharedMemorySize, SMHD);

    const dim3 blk(256);

    // composed projection: W_c = W_lin@W_K, b_c = b_lin@W_K + b_K (exact fp32)
    sgemm_nn<<<dim3(D / 128, 1), blk>>>(NF, D, D, W_lin, W_K, nullptr, nullptr, Wc, 0);
    bias_comp<<<1, D>>>(b_lin, W_K, b_K, bc);

    // candidate keys in ONE GEMM: ki = cand @ W_c + b_c
    sgemm_nn<<<dim3(D / 128, (NC + 127) / 128), blk>>>(NC, D, NF, cand_num, Wc, bc, nullptr, ki, 0);

    // query projections (two-stage: x needed for residual)
    sgemm_nn<<<dim3(D / 128, Bq / 128), blk>>>(Bq, D, NF, x_num, W_lin, b_lin, nullptr, xb, 0);
    sgemm_nn<<<dim3(D / 128, Bq / 128), blk>>>(Bq, D, D,  xb,    W_K,   b_K,   nullptr, kb, 0);

    // fused fp16 plane + norm (single pass over ki / kb)
    split_norm_f16<<<NC, 256>>>(ki, kif, nn2);
    split_norm_f16<<<Bq, 256>>>(kb, kbf, kk2);
    tsplit2<<<256, 256>>>(T_W1, D,  DI, T1h, T1l);
    tsplit2<<<256, 256>>>(T_W2, DI, D,  T2h, T2l);

    // fp16 single-plane distance (preselect) -> top-128 -> exact fp32 rescore
    hmma_dist_f16<<<dim3((NC + 127) / 128, Bq / 128), blk, SMHD>>>(
        Bq, NC, D, kbf, kif, kk2, nn2, d2);
    topk_kernel<<<Bq, 256>>>(d2, NC, I2b, KSEL);
    rescore<<<Bq, KSEL>>>(kb, ki, kk2, nn2, I2b, Ib);

    // gather (exact S + diff splits) + softmax
    gather_diff<<<Bq * CTX, 256>>>(kb, ki, Ib, cand_y, dfh, dfl, Sb, clsb);
    softmax96<<<Bq, 128>>>(Sb, wb);

    // tensor-core T-MLP (bf16 3-product)
    hmma_nt<<<dim3(DI / 128, BCTX / 128), blk, SMH>>>(
        BCTX, DI, D, dfh, dfl, T1h, T1l, T_b1,
        nullptr, mhh, mhl, F_BIAS | F_RELU | F_SP2);
    hmma_nt<<<dim3(D / 128, BCTX / 128), blk, SMH>>>(
        BCTX, D, DI, mhh, mhl, T2h, T2l, nullptr,
        Vb, nullptr, nullptr, F_CF);

    // aggregation + predictor + head (exact fp32)
    aggregate<<<Bq, 256>>>(xb, wb, Vb, clsb, Y_emb, xr);
    ln_kernel<<<Bq, 256>>>(xr, bp_ln_s, bp_ln_b, lnb);
    sgemm_nn<<<dim3(DI / 128, Bq / 128), blk>>>(Bq, DI, D,  lnb, bp_W1, bp_b1, nullptr, p1, 1);
    sgemm_nn<<<dim3(D / 128,  Bq / 128), blk>>>(Bq, D,  DI, p1,  bp_W2, bp_b2, xr,      x2, 0);
    head_kernel<<<Bq, 256>>>(x2, P_ln_s, P_ln_b, P_W, P_b, out);
}